// round 3
// baseline (speedup 1.0000x reference)
#include <cuda_runtime.h>

#define NN 50000
#define EE 800000
#define HH 8
#define HC 128
#define NEG 0.2f

// Scratch (device globals: allowed; no cudaMalloc anywhere)
__device__ float    g_h[NN * HC];      // x @ W_gat
__device__ float    g_skip[NN * HC];   // x @ W_skip
__device__ float    g_acc[NN * HC];    // sum of e_exp * h[src] per dst
__device__ float    g_asrc[NN * HH];
__device__ float    g_adst[NN * HH];
__device__ unsigned g_emax[NN * HH];   // order-preserving uint encoding of float max
__device__ float    g_denom[NN * HH];

// order-preserving float <-> uint mapping (for atomicMax on floats incl. negatives)
__device__ __forceinline__ unsigned fenc(float f) {
    unsigned u = __float_as_uint(f);
    return (u & 0x80000000u) ? ~u : (u | 0x80000000u);
}
__device__ __forceinline__ float fdec(unsigned u) {
    u = (u & 0x80000000u) ? (u & 0x7fffffffu) : ~u;
    return __uint_as_float(u);
}

// ---------------------------------------------------------------------------
// K0: zero accumulators. emax=0u encodes below every real float's encoding.
__global__ void k_init() {
    int i = blockIdx.x * blockDim.x + threadIdx.x;
    int stride = gridDim.x * blockDim.x;
    for (int j = i; j < NN * HC; j += stride) g_acc[j] = 0.0f;
    for (int j = i; j < NN * HH; j += stride) { g_denom[j] = 0.0f; g_emax[j] = 0u; }
}

// ---------------------------------------------------------------------------
// K1: dual GEMM. out[n,j] = sum_k X[n,k] * W[k,j].  M=NN, K=128, Ncols=128.
// blockIdx.y = 0 -> (W_gat, g_h), 1 -> (W_skip, g_skip).
// Tile: BM=64, BN=128, BK=32; 256 threads; each thread 8x4 micro-tile.
__global__ void k_gemm(const float* __restrict__ X,
                       const float* __restrict__ Wg,
                       const float* __restrict__ Ws) {
    const float* W  = (blockIdx.y == 0) ? Wg : Ws;
    float* out      = (blockIdx.y == 0) ? g_h : g_skip;

    __shared__ float xs[64 * 32];
    __shared__ float ws[32 * 128];

    int tid = threadIdx.x;
    int tx = tid & 31;     // column group: cols 4*tx .. 4*tx+3
    int ty = tid >> 5;     // row group: rows ty + 8*i
    int m0 = blockIdx.x * 64;

    float acc[8][4];
#pragma unroll
    for (int i = 0; i < 8; i++)
#pragma unroll
        for (int j = 0; j < 4; j++) acc[i][j] = 0.0f;

    for (int kb = 0; kb < 128; kb += 32) {
        // load xs: 64 rows x 32 cols (float4 per thread x2)
#pragma unroll
        for (int t = 0; t < 2; t++) {
            int idx = tid + t * 256;          // float4 idx 0..511
            int r = idx >> 3, c4 = idx & 7;
            int gm = m0 + r;
            float4 v = make_float4(0.f, 0.f, 0.f, 0.f);
            if (gm < NN) v = *(const float4*)&X[gm * 128 + kb + c4 * 4];
            *(float4*)&xs[r * 32 + c4 * 4] = v;
        }
        // load ws: 32 rows x 128 cols (float4 per thread x4)
#pragma unroll
        for (int t = 0; t < 4; t++) {
            int idx = tid + t * 256;          // float4 idx 0..1023
            int r = idx >> 5, c4 = idx & 31;
            *(float4*)&ws[r * 128 + c4 * 4] = *(const float4*)&W[(kb + r) * 128 + c4 * 4];
        }
        __syncthreads();
#pragma unroll
        for (int kk = 0; kk < 32; kk++) {
            float4 b = *(float4*)&ws[kk * 128 + tx * 4];
#pragma unroll
            for (int i = 0; i < 8; i++) {
                float a = xs[(ty + i * 8) * 32 + kk];
                acc[i][0] += a * b.x;
                acc[i][1] += a * b.y;
                acc[i][2] += a * b.z;
                acc[i][3] += a * b.w;
            }
        }
        __syncthreads();
    }
#pragma unroll
    for (int i = 0; i < 8; i++) {
        int gm = m0 + ty + i * 8;
        if (gm < NN)
            *(float4*)&out[gm * 128 + tx * 4] =
                make_float4(acc[i][0], acc[i][1], acc[i][2], acc[i][3]);
    }
}

// ---------------------------------------------------------------------------
// K2: per-node attention coefficients. One warp per node.
// lane l handles cols 4l..4l+3 (head = l>>2, att flat index = 4l+j).
__global__ void k_attn(const float* __restrict__ att_s, const float* __restrict__ att_d) {
    int t = blockIdx.x * blockDim.x + threadIdx.x;
    int n = t >> 5, lane = t & 31;
    if (n >= NN) return;
    float4 hv = *(const float4*)&g_h[n * HC + lane * 4];
    float4 as = *(const float4*)&att_s[lane * 4];
    float4 ad = *(const float4*)&att_d[lane * 4];
    float ps = hv.x * as.x + hv.y * as.y + hv.z * as.z + hv.w * as.w;
    float pd = hv.x * ad.x + hv.y * ad.y + hv.z * ad.z + hv.w * ad.w;
    ps += __shfl_xor_sync(0xffffffffu, ps, 1);
    ps += __shfl_xor_sync(0xffffffffu, ps, 2);
    pd += __shfl_xor_sync(0xffffffffu, pd, 1);
    pd += __shfl_xor_sync(0xffffffffu, pd, 2);
    if ((lane & 3) == 0) {
        g_asrc[n * HH + (lane >> 2)] = ps;
        g_adst[n * HH + (lane >> 2)] = pd;
    }
}

// ---------------------------------------------------------------------------
// K3: edge max pass. One thread per edge (incl. N self-loops appended).
// edge_index is int32 (JAX x64 disabled downgrades int64 -> int32).
__global__ void k_edge_max(const int* __restrict__ ei) {
    int e = blockIdx.x * blockDim.x + threadIdx.x;
    if (e >= EE + NN) return;
    int s, d;
    if (e < EE) { s = ei[e]; d = ei[EE + e]; }
    else        { s = d = e - EE; }
    float4 as0 = *(const float4*)&g_asrc[s * HH];
    float4 as1 = *(const float4*)&g_asrc[s * HH + 4];
    float4 ad0 = *(const float4*)&g_adst[d * HH];
    float4 ad1 = *(const float4*)&g_adst[d * HH + 4];
    float ev[8] = { as0.x + ad0.x, as0.y + ad0.y, as0.z + ad0.z, as0.w + ad0.w,
                    as1.x + ad1.x, as1.y + ad1.y, as1.z + ad1.z, as1.w + ad1.w };
#pragma unroll
    for (int h = 0; h < 8; h++) {
        float v = ev[h] > 0.f ? ev[h] : NEG * ev[h];
        atomicMax(&g_emax[d * HH + h], fenc(v));
    }
}

// ---------------------------------------------------------------------------
// K4: edge scatter pass. One warp per edge: lane l covers 4 floats of h[src],
// accumulates e_exp * h[src] into g_acc[dst] via red.global.add.v4.f32,
// and denom via scalar atomicAdd (one lane per head).
__global__ void k_edge_scatter(const int* __restrict__ ei) {
    int t = blockIdx.x * blockDim.x + threadIdx.x;
    int w = t >> 5, lane = t & 31;
    if (w >= EE + NN) return;
    int s, d;
    if (w < EE) { s = ei[w]; d = ei[EE + w]; }
    else        { s = d = w - EE; }
    int head = lane >> 2;
    float ev = g_asrc[s * HH + head] + g_adst[d * HH + head];
    ev = ev > 0.f ? ev : NEG * ev;
    float em = fdec(g_emax[d * HH + head]);
    float ex = __expf(ev - em);
    if ((lane & 3) == 0) atomicAdd(&g_denom[d * HH + head], ex);
    float4 hv = *(const float4*)&g_h[s * HC + lane * 4];
    float* p = &g_acc[d * HC + lane * 4];
    asm volatile("red.global.add.v4.f32 [%0], {%1,%2,%3,%4};"
                 :: "l"(p), "f"(ex * hv.x), "f"(ex * hv.y),
                    "f"(ex * hv.z), "f"(ex * hv.w)
                 : "memory");
}

// ---------------------------------------------------------------------------
// K5: finalize. One warp per node: normalize by denom, +bias, +0.1*skip,
// LayerNorm over 128 via warp reduce, ELU, write out.
__global__ void k_final(const float* __restrict__ bias,
                        const float* __restrict__ gamma,
                        const float* __restrict__ beta,
                        float* __restrict__ out) {
    int t = blockIdx.x * blockDim.x + threadIdx.x;
    int n = t >> 5, lane = t & 31;
    if (n >= NN) return;
    int head = lane >> 2;
    float4 a  = *(float4*)&g_acc[n * HC + lane * 4];
    float4 sk = *(float4*)&g_skip[n * HC + lane * 4];
    float4 b  = *(const float4*)&bias[lane * 4];
    float inv = 1.0f / g_denom[n * HH + head];
    float z[4];
    z[0] = a.x * inv + b.x + 0.1f * sk.x;
    z[1] = a.y * inv + b.y + 0.1f * sk.y;
    z[2] = a.z * inv + b.z + 0.1f * sk.z;
    z[3] = a.w * inv + b.w + 0.1f * sk.w;
    float sum = z[0] + z[1] + z[2] + z[3];
    float sq  = z[0] * z[0] + z[1] * z[1] + z[2] * z[2] + z[3] * z[3];
#pragma unroll
    for (int off = 16; off >= 1; off >>= 1) {
        sum += __shfl_xor_sync(0xffffffffu, sum, off);
        sq  += __shfl_xor_sync(0xffffffffu, sq, off);
    }
    float mu  = sum * (1.0f / 128.0f);
    float var = sq * (1.0f / 128.0f) - mu * mu;
    float rstd = rsqrtf(var + 1e-5f);
    float4 g  = *(const float4*)&gamma[lane * 4];
    float4 be = *(const float4*)&beta[lane * 4];
    float y[4];
    y[0] = (z[0] - mu) * rstd * g.x + be.x;
    y[1] = (z[1] - mu) * rstd * g.y + be.y;
    y[2] = (z[2] - mu) * rstd * g.z + be.z;
    y[3] = (z[3] - mu) * rstd * g.w + be.w;
#pragma unroll
    for (int j = 0; j < 4; j++) y[j] = y[j] > 0.f ? y[j] : expm1f(y[j]);
    *(float4*)&out[n * HC + lane * 4] = make_float4(y[0], y[1], y[2], y[3]);
}

// ---------------------------------------------------------------------------
extern "C" void kernel_launch(void* const* d_in, const int* in_sizes, int n_in,
                              void* d_out, int out_size) {
    const float* x       = (const float*)d_in[0];
    const int*   ei      = (const int*)d_in[1];
    const float* W_gat   = (const float*)d_in[2];
    const float* att_src = (const float*)d_in[3];
    const float* att_dst = (const float*)d_in[4];
    const float* bias    = (const float*)d_in[5];
    const float* W_skip  = (const float*)d_in[6];
    const float* gamma   = (const float*)d_in[7];
    const float* beta    = (const float*)d_in[8];
    float* out = (float*)d_out;

    k_init<<<1024, 256>>>();
    k_gemm<<<dim3((NN + 63) / 64, 2), 256>>>(x, W_gat, W_skip);
    k_attn<<<(NN * 32 + 255) / 256, 256>>>(att_src, att_dst);
    k_edge_max<<<(EE + NN + 255) / 256, 256>>>(ei);
    {
        long long threads = (long long)(EE + NN) * 32;
        k_edge_scatter<<<(unsigned)((threads + 255) / 256), 256>>>(ei);
    }
    k_final<<<(NN * 32 + 255) / 256, 256>>>(bias, gamma, beta, out);
}

// round 4
// speedup vs baseline: 1.6135x; 1.6135x over previous
#include <cuda_runtime.h>

#define NN 50000
#define EE 800000
#define HH 8
#define HC 128
#define NEG 0.2f
#define FULL 0xffffffffu

#define SCAN_T 1024
#define NB ((NN + SCAN_T - 1) / SCAN_T)   // 49

// Scratch (device globals; no cudaMalloc anywhere)
__device__ float g_h[NN * HC];        // x @ W_gat
__device__ float g_skip[NN * HC];     // x @ W_skip
__device__ float g_asrc[NN * HH];
__device__ float g_adst[NN * HH];
__device__ int   g_cnt[NN];           // in-degree histogram (excl. self-loop)
__device__ int   g_rowstart[NN + 1];  // CSR row offsets
__device__ int   g_cursor[NN];        // fill cursors
__device__ int   g_part[NB];          // scan partials
__device__ int   g_csr[EE];           // src ids grouped by dst

// ---------------------------------------------------------------------------
__global__ void k_zero() {
    int i = blockIdx.x * blockDim.x + threadIdx.x;
    if (i < NN) g_cnt[i] = 0;
}

// ---------------------------------------------------------------------------
// Fused dual GEMM + attention-dot epilogue.
// h = X@Wg, skip = X@Ws (M=NN, K=128, N=128). BM=64, BK=32, 256 threads,
// each thread an 8x4 micro-tile for BOTH outputs (64 accumulators).
// Epilogue: warp w owns rows {w + 8i}; lanes hold 4 cols each; attention dots
// per head reduce across groups of 4 lanes (head = lane>>2).
__global__ void __launch_bounds__(256)
k_gemm(const float* __restrict__ X,
       const float* __restrict__ Wg,
       const float* __restrict__ Ws,
       const float* __restrict__ att_s,
       const float* __restrict__ att_d) {
    __shared__ float xs[64 * 32];
    __shared__ float wsg[32 * 128];
    __shared__ float wss[32 * 128];

    int tid = threadIdx.x;
    int tx = tid & 31;   // lane: cols 4tx..4tx+3
    int ty = tid >> 5;   // warp: rows ty + 8i
    int m0 = blockIdx.x * 64;

    float ag[8][4], as[8][4];
#pragma unroll
    for (int i = 0; i < 8; i++)
#pragma unroll
        for (int j = 0; j < 4; j++) { ag[i][j] = 0.f; as[i][j] = 0.f; }

    for (int kb = 0; kb < 128; kb += 32) {
#pragma unroll
        for (int t = 0; t < 2; t++) {
            int idx = tid + t * 256;           // float4 idx 0..511
            int r = idx >> 3, c4 = idx & 7;
            int gm = m0 + r;
            float4 v = make_float4(0.f, 0.f, 0.f, 0.f);
            if (gm < NN) v = *(const float4*)&X[gm * 128 + kb + c4 * 4];
            *(float4*)&xs[r * 32 + c4 * 4] = v;
        }
#pragma unroll
        for (int t = 0; t < 4; t++) {
            int idx = tid + t * 256;           // float4 idx 0..1023
            int r = idx >> 5, c4 = idx & 31;
            *(float4*)&wsg[r * 128 + c4 * 4] = *(const float4*)&Wg[(kb + r) * 128 + c4 * 4];
            *(float4*)&wss[r * 128 + c4 * 4] = *(const float4*)&Ws[(kb + r) * 128 + c4 * 4];
        }
        __syncthreads();
#pragma unroll
        for (int kk = 0; kk < 32; kk++) {
            float4 bg = *(float4*)&wsg[kk * 128 + tx * 4];
            float4 bs = *(float4*)&wss[kk * 128 + tx * 4];
#pragma unroll
            for (int i = 0; i < 8; i++) {
                float a = xs[(ty + i * 8) * 32 + kk];
                ag[i][0] += a * bg.x; ag[i][1] += a * bg.y;
                ag[i][2] += a * bg.z; ag[i][3] += a * bg.w;
                as[i][0] += a * bs.x; as[i][1] += a * bs.y;
                as[i][2] += a * bs.z; as[i][3] += a * bs.w;
            }
        }
        __syncthreads();
    }

    float4 av_s = *(const float4*)&att_s[tx * 4];
    float4 av_d = *(const float4*)&att_d[tx * 4];
#pragma unroll
    for (int i = 0; i < 8; i++) {
        int gm = m0 + ty + i * 8;
        if (gm >= NN) continue;
        *(float4*)&g_h[gm * 128 + tx * 4] =
            make_float4(ag[i][0], ag[i][1], ag[i][2], ag[i][3]);
        *(float4*)&g_skip[gm * 128 + tx * 4] =
            make_float4(as[i][0], as[i][1], as[i][2], as[i][3]);
        float ps = ag[i][0] * av_s.x + ag[i][1] * av_s.y + ag[i][2] * av_s.z + ag[i][3] * av_s.w;
        float pd = ag[i][0] * av_d.x + ag[i][1] * av_d.y + ag[i][2] * av_d.z + ag[i][3] * av_d.w;
        ps += __shfl_xor_sync(FULL, ps, 1); ps += __shfl_xor_sync(FULL, ps, 2);
        pd += __shfl_xor_sync(FULL, pd, 1); pd += __shfl_xor_sync(FULL, pd, 2);
        if ((tx & 3) == 0) {
            g_asrc[gm * HH + (tx >> 2)] = ps;
            g_adst[gm * HH + (tx >> 2)] = pd;
        }
    }
}

// ---------------------------------------------------------------------------
__global__ void k_hist(const int* __restrict__ ei) {
    int e = blockIdx.x * blockDim.x + threadIdx.x;
    if (e < EE) atomicAdd(&g_cnt[ei[EE + e]], 1);
}

// Block-wide exclusive scan helper (blockDim.x <= 1024)
__device__ __forceinline__ int block_excl_scan(int v, int* warpsums) {
    int lane = threadIdx.x & 31, wid = threadIdx.x >> 5;
    int x = v;
#pragma unroll
    for (int off = 1; off < 32; off <<= 1) {
        int y = __shfl_up_sync(FULL, x, off);
        if (lane >= off) x += y;
    }
    if (lane == 31) warpsums[wid] = x;
    __syncthreads();
    if (wid == 0) {
        int nw = (blockDim.x + 31) >> 5;
        int s = (lane < nw) ? warpsums[lane] : 0;
#pragma unroll
        for (int off = 1; off < 32; off <<= 1) {
            int y = __shfl_up_sync(FULL, s, off);
            if (lane >= off) s += y;
        }
        warpsums[lane] = s;  // inclusive warp totals
    }
    __syncthreads();
    int base = (wid > 0) ? warpsums[wid - 1] : 0;
    return base + x - v;
}

__global__ void k_scan_a() {
    __shared__ int ws[32];
    int i = blockIdx.x * SCAN_T + threadIdx.x;
    int v = (i < NN) ? g_cnt[i] : 0;
    int ex = block_excl_scan(v, ws);
    if (i < NN) g_rowstart[i] = ex;
    if (threadIdx.x == SCAN_T - 1) g_part[blockIdx.x] = ex + v;
}

__global__ void k_scan_b() {
    __shared__ int ws[32];
    int t = threadIdx.x;
    int v = (t < NB) ? g_part[t] : 0;
    int ex = block_excl_scan(v, ws);
    if (t < NB) g_part[t] = ex;
}

__global__ void k_scan_c() {
    int i = blockIdx.x * SCAN_T + threadIdx.x;
    if (i < NN) {
        int r = g_rowstart[i] + g_part[blockIdx.x];
        g_rowstart[i] = r;
        g_cursor[i] = r;
    }
    if (i == 0) g_rowstart[NN] = EE;
}

__global__ void k_fill(const int* __restrict__ ei) {
    int e = blockIdx.x * blockDim.x + threadIdx.x;
    if (e >= EE) return;
    int s = ei[e], d = ei[EE + e];
    int pos = atomicAdd(&g_cursor[d], 1);
    g_csr[pos] = s;
}

// ---------------------------------------------------------------------------
// Gather + finalize: one warp per dst node. Register-resident accumulation of
// sum(exp(e) * h[src]) over CSR neighbors + the self-loop (no max shift:
// softmax is shift-invariant and logits are O(1)). Then denom division, bias,
// skip, LayerNorm, ELU, store — all in-warp.
__global__ void __launch_bounds__(256)
k_gather(const float* __restrict__ bias,
         const float* __restrict__ gamma,
         const float* __restrict__ beta,
         float* __restrict__ out) {
    int t = blockIdx.x * blockDim.x + threadIdx.x;
    int n = t >> 5, lane = t & 31;
    if (n >= NN) return;
    int head = lane >> 2;

    float adn = g_adst[n * HH + head];
    float a0 = 0.f, a1 = 0.f, a2 = 0.f, a3 = 0.f, den = 0.f;

    // self-loop
    {
        float e = g_asrc[n * HH + head] + adn;
        e = e > 0.f ? e : NEG * e;
        float ex = __expf(e);
        float4 hv = *(const float4*)&g_h[n * HC + lane * 4];
        a0 += ex * hv.x; a1 += ex * hv.y; a2 += ex * hv.z; a3 += ex * hv.w;
        den += ex;
    }

    int start = g_rowstart[n], end = g_rowstart[n + 1];
    for (int base = start; base < end; base += 32) {
        int j = base + lane;
        int sj = (j < end) ? g_csr[j] : 0;
        int m = min(32, end - base);
        int k = 0;
        for (; k + 4 <= m; k += 4) {
            int s0 = __shfl_sync(FULL, sj, k);
            int s1 = __shfl_sync(FULL, sj, k + 1);
            int s2 = __shfl_sync(FULL, sj, k + 2);
            int s3 = __shfl_sync(FULL, sj, k + 3);
            float e0 = g_asrc[s0 * HH + head] + adn;
            float e1 = g_asrc[s1 * HH + head] + adn;
            float e2 = g_asrc[s2 * HH + head] + adn;
            float e3 = g_asrc[s3 * HH + head] + adn;
            e0 = e0 > 0.f ? e0 : NEG * e0;
            e1 = e1 > 0.f ? e1 : NEG * e1;
            e2 = e2 > 0.f ? e2 : NEG * e2;
            e3 = e3 > 0.f ? e3 : NEG * e3;
            float x0 = __expf(e0), x1 = __expf(e1);
            float x2 = __expf(e2), x3 = __expf(e3);
            float4 h0 = *(const float4*)&g_h[s0 * HC + lane * 4];
            float4 h1 = *(const float4*)&g_h[s1 * HC + lane * 4];
            float4 h2 = *(const float4*)&g_h[s2 * HC + lane * 4];
            float4 h3 = *(const float4*)&g_h[s3 * HC + lane * 4];
            a0 += x0 * h0.x; a1 += x0 * h0.y; a2 += x0 * h0.z; a3 += x0 * h0.w;
            a0 += x1 * h1.x; a1 += x1 * h1.y; a2 += x1 * h1.z; a3 += x1 * h1.w;
            a0 += x2 * h2.x; a1 += x2 * h2.y; a2 += x2 * h2.z; a3 += x2 * h2.w;
            a0 += x3 * h3.x; a1 += x3 * h3.y; a2 += x3 * h3.z; a3 += x3 * h3.w;
            den += x0 + x1 + x2 + x3;
        }
        for (; k < m; k++) {
            int s = __shfl_sync(FULL, sj, k);
            float e = g_asrc[s * HH + head] + adn;
            e = e > 0.f ? e : NEG * e;
            float ex = __expf(e);
            float4 hv = *(const float4*)&g_h[s * HC + lane * 4];
            a0 += ex * hv.x; a1 += ex * hv.y; a2 += ex * hv.z; a3 += ex * hv.w;
            den += ex;
        }
    }

    float inv = 1.0f / den;
    float4 sk = *(const float4*)&g_skip[n * HC + lane * 4];
    float4 b  = *(const float4*)&bias[lane * 4];
    float z0 = a0 * inv + b.x + 0.1f * sk.x;
    float z1 = a1 * inv + b.y + 0.1f * sk.y;
    float z2 = a2 * inv + b.z + 0.1f * sk.z;
    float z3 = a3 * inv + b.w + 0.1f * sk.w;

    float sum = z0 + z1 + z2 + z3;
    float sq  = z0 * z0 + z1 * z1 + z2 * z2 + z3 * z3;
#pragma unroll
    for (int off = 16; off >= 1; off >>= 1) {
        sum += __shfl_xor_sync(FULL, sum, off);
        sq  += __shfl_xor_sync(FULL, sq, off);
    }
    float mu   = sum * (1.0f / 128.0f);
    float var  = sq * (1.0f / 128.0f) - mu * mu;
    float rstd = rsqrtf(var + 1e-5f);
    float4 g  = *(const float4*)&gamma[lane * 4];
    float4 be = *(const float4*)&beta[lane * 4];
    float y0 = (z0 - mu) * rstd * g.x + be.x;
    float y1 = (z1 - mu) * rstd * g.y + be.y;
    float y2 = (z2 - mu) * rstd * g.z + be.z;
    float y3 = (z3 - mu) * rstd * g.w + be.w;
    y0 = y0 > 0.f ? y0 : expm1f(y0);
    y1 = y1 > 0.f ? y1 : expm1f(y1);
    y2 = y2 > 0.f ? y2 : expm1f(y2);
    y3 = y3 > 0.f ? y3 : expm1f(y3);
    *(float4*)&out[n * HC + lane * 4] = make_float4(y0, y1, y2, y3);
}

// ---------------------------------------------------------------------------
extern "C" void kernel_launch(void* const* d_in, const int* in_sizes, int n_in,
                              void* d_out, int out_size) {
    const float* x       = (const float*)d_in[0];
    const int*   ei      = (const int*)d_in[1];
    const float* W_gat   = (const float*)d_in[2];
    const float* att_src = (const float*)d_in[3];
    const float* att_dst = (const float*)d_in[4];
    const float* bias    = (const float*)d_in[5];
    const float* W_skip  = (const float*)d_in[6];
    const float* gamma   = (const float*)d_in[7];
    const float* beta    = (const float*)d_in[8];
    float* out = (float*)d_out;

    k_zero<<<(NN + 255) / 256, 256>>>();
    k_gemm<<<(NN + 63) / 64, 256>>>(x, W_gat, W_skip, att_src, att_dst);
    k_hist<<<(EE + 255) / 256, 256>>>(ei);
    k_scan_a<<<NB, SCAN_T>>>();
    k_scan_b<<<1, SCAN_T>>>();
    k_scan_c<<<NB, SCAN_T>>>();
    k_fill<<<(EE + 255) / 256, 256>>>(ei);
    k_gather<<<(NN * 32 + 255) / 256, 256>>>(bias, gamma, beta, out);
}

// round 5
// speedup vs baseline: 1.6860x; 1.0449x over previous
#include <cuda_runtime.h>
#include <cuda_fp16.h>

#define NN 50000
#define EE 800000
#define HH 8
#define HC 128
#define NEG 0.2f
#define FULL 0xffffffffu

#define SCAN_T 1024
#define NB ((NN + SCAN_T - 1) / SCAN_T)   // 49

// Scratch (device globals; no cudaMalloc anywhere)
__device__ __half2 g_hh[NN * 64];     // x @ W_gat, fp16 (messages only)
__device__ __half2 g_sk[NN * 64];     // x @ W_skip, fp16
__device__ float   g_asrc[NN * HH];   // fp32 attention logit parts (exact)
__device__ float   g_adst[NN * HH];
__device__ int     g_cnt[NN];
__device__ int     g_rowstart[NN + 1];
__device__ int     g_cursor[NN];
__device__ int     g_part[NB];
__device__ int     g_csr[EE];

// ---------------------------------------------------------------------------
__global__ void k_zero() {
    int i = blockIdx.x * blockDim.x + threadIdx.x;
    if (i < NN) g_cnt[i] = 0;
}

// ---------------------------------------------------------------------------
// Fused dual GEMM + attention-dot epilogue. fp32 math; fp16 stores for h/skip.
__global__ void __launch_bounds__(256)
k_gemm(const float* __restrict__ X,
       const float* __restrict__ Wg,
       const float* __restrict__ Ws,
       const float* __restrict__ att_s,
       const float* __restrict__ att_d) {
    __shared__ float xs[64 * 32];
    __shared__ float wsg[32 * 128];
    __shared__ float wss[32 * 128];

    int tid = threadIdx.x;
    int tx = tid & 31;
    int ty = tid >> 5;
    int m0 = blockIdx.x * 64;

    float ag[8][4], as[8][4];
#pragma unroll
    for (int i = 0; i < 8; i++)
#pragma unroll
        for (int j = 0; j < 4; j++) { ag[i][j] = 0.f; as[i][j] = 0.f; }

    for (int kb = 0; kb < 128; kb += 32) {
#pragma unroll
        for (int t = 0; t < 2; t++) {
            int idx = tid + t * 256;
            int r = idx >> 3, c4 = idx & 7;
            int gm = m0 + r;
            float4 v = make_float4(0.f, 0.f, 0.f, 0.f);
            if (gm < NN) v = *(const float4*)&X[gm * 128 + kb + c4 * 4];
            *(float4*)&xs[r * 32 + c4 * 4] = v;
        }
#pragma unroll
        for (int t = 0; t < 4; t++) {
            int idx = tid + t * 256;
            int r = idx >> 5, c4 = idx & 31;
            *(float4*)&wsg[r * 128 + c4 * 4] = *(const float4*)&Wg[(kb + r) * 128 + c4 * 4];
            *(float4*)&wss[r * 128 + c4 * 4] = *(const float4*)&Ws[(kb + r) * 128 + c4 * 4];
        }
        __syncthreads();
#pragma unroll
        for (int kk = 0; kk < 32; kk++) {
            float4 bg = *(float4*)&wsg[kk * 128 + tx * 4];
            float4 bs = *(float4*)&wss[kk * 128 + tx * 4];
#pragma unroll
            for (int i = 0; i < 8; i++) {
                float a = xs[(ty + i * 8) * 32 + kk];
                ag[i][0] += a * bg.x; ag[i][1] += a * bg.y;
                ag[i][2] += a * bg.z; ag[i][3] += a * bg.w;
                as[i][0] += a * bs.x; as[i][1] += a * bs.y;
                as[i][2] += a * bs.z; as[i][3] += a * bs.w;
            }
        }
        __syncthreads();
    }

    float4 av_s = *(const float4*)&att_s[tx * 4];
    float4 av_d = *(const float4*)&att_d[tx * 4];
#pragma unroll
    for (int i = 0; i < 8; i++) {
        int gm = m0 + ty + i * 8;
        if (gm >= NN) continue;
        // fp16 stores (one 8B store each)
        __half2 h01 = __floats2half2_rn(ag[i][0], ag[i][1]);
        __half2 h23 = __floats2half2_rn(ag[i][2], ag[i][3]);
        uint2 uh;
        uh.x = *(unsigned*)&h01; uh.y = *(unsigned*)&h23;
        *(uint2*)&g_hh[gm * 64 + tx * 2] = uh;
        __half2 s01 = __floats2half2_rn(as[i][0], as[i][1]);
        __half2 s23 = __floats2half2_rn(as[i][2], as[i][3]);
        uint2 us;
        us.x = *(unsigned*)&s01; us.y = *(unsigned*)&s23;
        *(uint2*)&g_sk[gm * 64 + tx * 2] = us;
        // fp32-exact attention logit parts
        float ps = ag[i][0] * av_s.x + ag[i][1] * av_s.y + ag[i][2] * av_s.z + ag[i][3] * av_s.w;
        float pd = ag[i][0] * av_d.x + ag[i][1] * av_d.y + ag[i][2] * av_d.z + ag[i][3] * av_d.w;
        ps += __shfl_xor_sync(FULL, ps, 1); ps += __shfl_xor_sync(FULL, ps, 2);
        pd += __shfl_xor_sync(FULL, pd, 1); pd += __shfl_xor_sync(FULL, pd, 2);
        if ((tx & 3) == 0) {
            g_asrc[gm * HH + (tx >> 2)] = ps;
            g_adst[gm * HH + (tx >> 2)] = pd;
        }
    }
}

// ---------------------------------------------------------------------------
__global__ void k_hist(const int* __restrict__ ei) {
    int e = blockIdx.x * blockDim.x + threadIdx.x;
    if (e < EE) atomicAdd(&g_cnt[ei[EE + e]], 1);
}

__device__ __forceinline__ int block_excl_scan(int v, int* warpsums) {
    int lane = threadIdx.x & 31, wid = threadIdx.x >> 5;
    int x = v;
#pragma unroll
    for (int off = 1; off < 32; off <<= 1) {
        int y = __shfl_up_sync(FULL, x, off);
        if (lane >= off) x += y;
    }
    if (lane == 31) warpsums[wid] = x;
    __syncthreads();
    if (wid == 0) {
        int nw = (blockDim.x + 31) >> 5;
        int s = (lane < nw) ? warpsums[lane] : 0;
#pragma unroll
        for (int off = 1; off < 32; off <<= 1) {
            int y = __shfl_up_sync(FULL, s, off);
            if (lane >= off) s += y;
        }
        warpsums[lane] = s;
    }
    __syncthreads();
    int base = (wid > 0) ? warpsums[wid - 1] : 0;
    return base + x - v;
}

__global__ void k_scan_a() {
    __shared__ int ws[32];
    int i = blockIdx.x * SCAN_T + threadIdx.x;
    int v = (i < NN) ? g_cnt[i] : 0;
    int ex = block_excl_scan(v, ws);
    if (i < NN) g_rowstart[i] = ex;
    if (threadIdx.x == SCAN_T - 1) g_part[blockIdx.x] = ex + v;
}

// scan_b + scan_c merged: each block sums the partials of preceding blocks.
__global__ void k_scan_c() {
    __shared__ int parts[NB];
    if (threadIdx.x < NB) parts[threadIdx.x] = g_part[threadIdx.x];
    __syncthreads();
    int pre = 0;
    for (int j = 0; j < NB; j++)
        if (j < blockIdx.x) pre += parts[j];
    int i = blockIdx.x * SCAN_T + threadIdx.x;
    if (i < NN) {
        int r = g_rowstart[i] + pre;
        g_rowstart[i] = r;
        g_cursor[i] = r;
    }
    if (i == 0) g_rowstart[NN] = EE;
}

__global__ void k_fill(const int* __restrict__ ei) {
    int e = blockIdx.x * blockDim.x + threadIdx.x;
    if (e >= EE) return;
    int s = ei[e], d = ei[EE + e];
    int pos = atomicAdd(&g_cursor[d], 1);
    g_csr[pos] = s;
}

// ---------------------------------------------------------------------------
// Gather + finalize: warp per dst node; fp16 message payload, fp32 math.
__device__ __forceinline__ void acc_h(int s, int lane, float ex,
                                      float& a0, float& a1, float& a2, float& a3) {
    uint2 u = *(const uint2*)&g_hh[s * 64 + lane * 2];
    float2 f0 = __half22float2(*reinterpret_cast<__half2*>(&u.x));
    float2 f1 = __half22float2(*reinterpret_cast<__half2*>(&u.y));
    a0 += ex * f0.x; a1 += ex * f0.y; a2 += ex * f1.x; a3 += ex * f1.y;
}

__global__ void __launch_bounds__(256)
k_gather(const float* __restrict__ bias,
         const float* __restrict__ gamma,
         const float* __restrict__ beta,
         float* __restrict__ out) {
    int t = blockIdx.x * blockDim.x + threadIdx.x;
    int n = t >> 5, lane = t & 31;
    if (n >= NN) return;
    int head = lane >> 2;

    float adn = g_adst[n * HH + head];
    float a0 = 0.f, a1 = 0.f, a2 = 0.f, a3 = 0.f, den = 0.f;

    // self-loop
    {
        float e = g_asrc[n * HH + head] + adn;
        e = e > 0.f ? e : NEG * e;
        float ex = __expf(e);
        acc_h(n, lane, ex, a0, a1, a2, a3);
        den += ex;
    }

    int start = g_rowstart[n], end = g_rowstart[n + 1];
    for (int base = start; base < end; base += 32) {
        int j = base + lane;
        int sj = (j < end) ? g_csr[j] : 0;
        int m = min(32, end - base);
        int k = 0;
        for (; k + 4 <= m; k += 4) {
            int s0 = __shfl_sync(FULL, sj, k);
            int s1 = __shfl_sync(FULL, sj, k + 1);
            int s2 = __shfl_sync(FULL, sj, k + 2);
            int s3 = __shfl_sync(FULL, sj, k + 3);
            float e0 = g_asrc[s0 * HH + head] + adn;
            float e1 = g_asrc[s1 * HH + head] + adn;
            float e2 = g_asrc[s2 * HH + head] + adn;
            float e3 = g_asrc[s3 * HH + head] + adn;
            e0 = e0 > 0.f ? e0 : NEG * e0;
            e1 = e1 > 0.f ? e1 : NEG * e1;
            e2 = e2 > 0.f ? e2 : NEG * e2;
            e3 = e3 > 0.f ? e3 : NEG * e3;
            float x0 = __expf(e0), x1 = __expf(e1);
            float x2 = __expf(e2), x3 = __expf(e3);
            acc_h(s0, lane, x0, a0, a1, a2, a3);
            acc_h(s1, lane, x1, a0, a1, a2, a3);
            acc_h(s2, lane, x2, a0, a1, a2, a3);
            acc_h(s3, lane, x3, a0, a1, a2, a3);
            den += x0 + x1 + x2 + x3;
        }
        for (; k < m; k++) {
            int s = __shfl_sync(FULL, sj, k);
            float e = g_asrc[s * HH + head] + adn;
            e = e > 0.f ? e : NEG * e;
            float ex = __expf(e);
            acc_h(s, lane, ex, a0, a1, a2, a3);
            den += ex;
        }
    }

    float inv = 1.0f / den;
    uint2 us = *(const uint2*)&g_sk[n * 64 + lane * 2];
    float2 s0 = __half22float2(*reinterpret_cast<__half2*>(&us.x));
    float2 s1 = __half22float2(*reinterpret_cast<__half2*>(&us.y));
    float4 b  = *(const float4*)&bias[lane * 4];
    float z0 = a0 * inv + b.x + 0.1f * s0.x;
    float z1 = a1 * inv + b.y + 0.1f * s0.y;
    float z2 = a2 * inv + b.z + 0.1f * s1.x;
    float z3 = a3 * inv + b.w + 0.1f * s1.y;

    float sum = z0 + z1 + z2 + z3;
    float sq  = z0 * z0 + z1 * z1 + z2 * z2 + z3 * z3;
#pragma unroll
    for (int off = 16; off >= 1; off >>= 1) {
        sum += __shfl_xor_sync(FULL, sum, off);
        sq  += __shfl_xor_sync(FULL, sq, off);
    }
    float mu   = sum * (1.0f / 128.0f);
    float var  = sq * (1.0f / 128.0f) - mu * mu;
    float rstd = rsqrtf(var + 1e-5f);
    float4 g  = *(const float4*)&gamma[lane * 4];
    float4 be = *(const float4*)&beta[lane * 4];
    float y0 = (z0 - mu) * rstd * g.x + be.x;
    float y1 = (z1 - mu) * rstd * g.y + be.y;
    float y2 = (z2 - mu) * rstd * g.z + be.z;
    float y3 = (z3 - mu) * rstd * g.w + be.w;
    y0 = y0 > 0.f ? y0 : expm1f(y0);
    y1 = y1 > 0.f ? y1 : expm1f(y1);
    y2 = y2 > 0.f ? y2 : expm1f(y2);
    y3 = y3 > 0.f ? y3 : expm1f(y3);
    *(float4*)&out[n * HC + lane * 4] = make_float4(y0, y1, y2, y3);
}

// ---------------------------------------------------------------------------
extern "C" void kernel_launch(void* const* d_in, const int* in_sizes, int n_in,
                              void* d_out, int out_size) {
    const float* x       = (const float*)d_in[0];
    const int*   ei      = (const int*)d_in[1];
    const float* W_gat   = (const float*)d_in[2];
    const float* att_src = (const float*)d_in[3];
    const float* att_dst = (const float*)d_in[4];
    const float* bias    = (const float*)d_in[5];
    const float* W_skip  = (const float*)d_in[6];
    const float* gamma   = (const float*)d_in[7];
    const float* beta    = (const float*)d_in[8];
    float* out = (float*)d_out;

    k_zero<<<(NN + 255) / 256, 256>>>();
    k_gemm<<<(NN + 63) / 64, 256>>>(x, W_gat, W_skip, att_src, att_dst);
    k_hist<<<(EE + 255) / 256, 256>>>(ei);
    k_scan_a<<<NB, SCAN_T>>>();
    k_scan_c<<<NB, SCAN_T>>>();
    k_fill<<<(EE + 255) / 256, 256>>>(ei);
    k_gather<<<(NN * 32 + 255) / 256, 256>>>(bias, gamma, beta, out);
}

// round 6
// speedup vs baseline: 1.7775x; 1.0543x over previous
#include <cuda_runtime.h>
#include <cuda_fp16.h>
#include <cuda_bf16.h>

#define NN 50000
#define EE 800000
#define HH 8
#define HC 128
#define NEG 0.2f
#define FULL 0xffffffffu

#define SCAN_T 1024
#define NB ((NN + SCAN_T - 1) / SCAN_T)   // 49

// Scratch (device globals; no cudaMalloc anywhere)
__device__ __nv_bfloat16 g_xs[NN * 384];   // [Xhi | Xhi | Xlo] per row
__device__ __nv_bfloat16 g_wc[256 * 384];  // W^T: row n, k-cols [Whi | Wlo | Whi]
__device__ __half2 g_hh[NN * 64];          // h  (fp16 messages)
__device__ __half2 g_sk[NN * 64];          // skip (fp16)
__device__ float   g_asrc[NN * HH];
__device__ float   g_adst[NN * HH];
__device__ int     g_cnt[NN];
__device__ int     g_rowstart[NN + 1];
__device__ int     g_cursor[NN];
__device__ int     g_part[NB];
__device__ int     g_csr[EE];

// ---------------------------------------------------------------------------
__global__ void k_zero() {
    int i = blockIdx.x * blockDim.x + threadIdx.x;
    if (i < NN) g_cnt[i] = 0;
}

// ---------------------------------------------------------------------------
// Split X into bf16 hi/lo: g_xs[n] = [hi(0:128) | hi(128:256) | lo(256:384)]
__global__ void k_prep(const float* __restrict__ X) {
    int t = blockIdx.x * blockDim.x + threadIdx.x;
    int n = t >> 5, c4 = (t & 31) * 4;
    if (n >= NN) return;
    float4 v = *(const float4*)&X[n * 128 + c4];
    __nv_bfloat16 h0 = __float2bfloat16_rn(v.x);
    __nv_bfloat16 h1 = __float2bfloat16_rn(v.y);
    __nv_bfloat16 h2 = __float2bfloat16_rn(v.z);
    __nv_bfloat16 h3 = __float2bfloat16_rn(v.w);
    __nv_bfloat16 l0 = __float2bfloat16_rn(v.x - __bfloat162float(h0));
    __nv_bfloat16 l1 = __float2bfloat16_rn(v.y - __bfloat162float(h1));
    __nv_bfloat16 l2 = __float2bfloat16_rn(v.z - __bfloat162float(h2));
    __nv_bfloat16 l3 = __float2bfloat16_rn(v.w - __bfloat162float(h3));
    __nv_bfloat16 hi4[4] = {h0, h1, h2, h3};
    __nv_bfloat16 lo4[4] = {l0, l1, l2, l3};
    long base = (long)n * 384;
    *(uint2*)&g_xs[base + c4]       = *(uint2*)hi4;
    *(uint2*)&g_xs[base + 128 + c4] = *(uint2*)hi4;
    *(uint2*)&g_xs[base + 256 + c4] = *(uint2*)lo4;
}

// Build transposed split weights: g_wc[n][k], n in 0..255 (gat|skip),
// k 0-127 = hi(W[k][n]), 128-255 = lo, 256-383 = hi.
__global__ void k_prepw(const float* __restrict__ Wg, const float* __restrict__ Ws) {
    int t = blockIdx.x * blockDim.x + threadIdx.x;  // 256*96 groups of 4
    if (t >= 256 * 96) return;
    int n = t / 96, kq = t % 96;
    int k0 = kq * 4;
    __nv_bfloat16 out4[4];
#pragma unroll
    for (int j = 0; j < 4; j++) {
        int k = k0 + j;
        int kk = k & 127;
        float w = (n < 128) ? Wg[kk * 128 + n] : Ws[kk * 128 + n - 128];
        __nv_bfloat16 hi = __float2bfloat16_rn(w);
        if (k >= 128 && k < 256) {
            out4[j] = __float2bfloat16_rn(w - __bfloat162float(hi));
        } else {
            out4[j] = hi;
        }
    }
    *(uint2*)&g_wc[n * 384 + k0] = *(uint2*)out4;
}

// ---------------------------------------------------------------------------
// Tensor-core GEMM: C[m,n] = sum_k g_xs[m,k] * g_wc[n,k]  (K=384 bf16, fp32 acc)
// grid.y = 0 -> n cols 0-127 (h + attention dots), 1 -> cols 128-255 (skip).
// Block: 256 thr = 8 warps, warp grid 4(M)x2(N), warp tile 32x64.
__global__ void __launch_bounds__(256)
k_mm(const float* __restrict__ att_s, const float* __restrict__ att_d) {
    __shared__ __nv_bfloat16 As[128 * 40];
    __shared__ __nv_bfloat16 Bs[128 * 40];
    int tid = threadIdx.x;
    int wid = tid >> 5, lane = tid & 31;
    int g = lane >> 2, t = lane & 3;
    int m0 = blockIdx.x * 128;
    int gy = blockIdx.y;
    int wrow = (wid >> 1) * 32, wcol = (wid & 1) * 64;

    float d[2][8][4];
#pragma unroll
    for (int mi = 0; mi < 2; mi++)
#pragma unroll
        for (int ni = 0; ni < 8; ni++)
#pragma unroll
            for (int j = 0; j < 4; j++) d[mi][ni][j] = 0.f;

    for (int kb = 0; kb < 384; kb += 32) {
#pragma unroll
        for (int tt = 0; tt < 2; tt++) {
            int idx = tid + tt * 256;          // 0..511
            int r = idx >> 2, c8 = (idx & 3) * 8;
            int gm = m0 + r;
            uint4 v = make_uint4(0, 0, 0, 0);
            if (gm < NN) v = *(const uint4*)&g_xs[(long)gm * 384 + kb + c8];
            *(uint4*)&As[r * 40 + c8] = v;
            *(uint4*)&Bs[r * 40 + c8] =
                *(const uint4*)&g_wc[(gy * 128 + r) * 384 + kb + c8];
        }
        __syncthreads();
#pragma unroll
        for (int kk = 0; kk < 32; kk += 16) {
            unsigned a[2][4], b[8][2];
#pragma unroll
            for (int mi = 0; mi < 2; mi++) {
                int rb = wrow + 16 * mi;
                a[mi][0] = *(unsigned*)&As[(rb + g) * 40 + kk + 2 * t];
                a[mi][1] = *(unsigned*)&As[(rb + g + 8) * 40 + kk + 2 * t];
                a[mi][2] = *(unsigned*)&As[(rb + g) * 40 + kk + 2 * t + 8];
                a[mi][3] = *(unsigned*)&As[(rb + g + 8) * 40 + kk + 2 * t + 8];
            }
#pragma unroll
            for (int ni = 0; ni < 8; ni++) {
                int nb = wcol + 8 * ni + g;
                b[ni][0] = *(unsigned*)&Bs[nb * 40 + kk + 2 * t];
                b[ni][1] = *(unsigned*)&Bs[nb * 40 + kk + 2 * t + 8];
            }
#pragma unroll
            for (int mi = 0; mi < 2; mi++)
#pragma unroll
                for (int ni = 0; ni < 8; ni++) {
                    asm volatile(
                        "mma.sync.aligned.m16n8k16.row.col.f32.bf16.bf16.f32 "
                        "{%0,%1,%2,%3}, {%4,%5,%6,%7}, {%8,%9}, {%0,%1,%2,%3};\n"
                        : "+f"(d[mi][ni][0]), "+f"(d[mi][ni][1]),
                          "+f"(d[mi][ni][2]), "+f"(d[mi][ni][3])
                        : "r"(a[mi][0]), "r"(a[mi][1]), "r"(a[mi][2]), "r"(a[mi][3]),
                          "r"(b[ni][0]), "r"(b[ni][1]));
                }
        }
        __syncthreads();
    }

    // Epilogue. Lane owns rows r0 = base+g, r1 = r0+8 and cols c0=wcol+8ni+2t, c0+1.
    __half2* dstp = (gy == 0) ? g_hh : g_sk;
#pragma unroll
    for (int mi = 0; mi < 2; mi++) {
        int r0 = m0 + wrow + 16 * mi + g;
        int r1 = r0 + 8;
#pragma unroll
        for (int ni = 0; ni < 8; ni++) {
            int pidx = wcol / 2 + 4 * ni + t;   // half2 index (col/2)
            if (r0 < NN) dstp[r0 * 64 + pidx] = __floats2half2_rn(d[mi][ni][0], d[mi][ni][1]);
            if (r1 < NN) dstp[r1 * 64 + pidx] = __floats2half2_rn(d[mi][ni][2], d[mi][ni][3]);
        }
        if (gy == 0) {
            // attention dots: 4 heads per warp-half (head = wcol/16 + lh)
#pragma unroll
            for (int lh = 0; lh < 4; lh++) {
                float ps0 = 0.f, pd0 = 0.f, ps1 = 0.f, pd1 = 0.f;
#pragma unroll
                for (int j = 0; j < 2; j++) {
                    int ni = 2 * lh + j;
                    int c0 = wcol + 8 * ni + 2 * t;
                    float as0 = att_s[c0], as1 = att_s[c0 + 1];
                    float ad0 = att_d[c0], ad1 = att_d[c0 + 1];
                    ps0 += d[mi][ni][0] * as0 + d[mi][ni][1] * as1;
                    pd0 += d[mi][ni][0] * ad0 + d[mi][ni][1] * ad1;
                    ps1 += d[mi][ni][2] * as0 + d[mi][ni][3] * as1;
                    pd1 += d[mi][ni][2] * ad0 + d[mi][ni][3] * ad1;
                }
                ps0 += __shfl_xor_sync(FULL, ps0, 1); ps0 += __shfl_xor_sync(FULL, ps0, 2);
                pd0 += __shfl_xor_sync(FULL, pd0, 1); pd0 += __shfl_xor_sync(FULL, pd0, 2);
                ps1 += __shfl_xor_sync(FULL, ps1, 1); ps1 += __shfl_xor_sync(FULL, ps1, 2);
                pd1 += __shfl_xor_sync(FULL, pd1, 1); pd1 += __shfl_xor_sync(FULL, pd1, 2);
                int head = wcol / 16 + lh;
                if (t == 0) {
                    if (r0 < NN) { g_asrc[r0 * HH + head] = ps0; g_adst[r0 * HH + head] = pd0; }
                    if (r1 < NN) { g_asrc[r1 * HH + head] = ps1; g_adst[r1 * HH + head] = pd1; }
                }
            }
        }
    }
}

// ---------------------------------------------------------------------------
__global__ void k_hist(const int* __restrict__ ei) {
    int e = blockIdx.x * blockDim.x + threadIdx.x;
    if (e < EE) atomicAdd(&g_cnt[ei[EE + e]], 1);
}

__device__ __forceinline__ int block_excl_scan(int v, int* warpsums) {
    int lane = threadIdx.x & 31, wid = threadIdx.x >> 5;
    int x = v;
#pragma unroll
    for (int off = 1; off < 32; off <<= 1) {
        int y = __shfl_up_sync(FULL, x, off);
        if (lane >= off) x += y;
    }
    if (lane == 31) warpsums[wid] = x;
    __syncthreads();
    if (wid == 0) {
        int nw = (blockDim.x + 31) >> 5;
        int s = (lane < nw) ? warpsums[lane] : 0;
#pragma unroll
        for (int off = 1; off < 32; off <<= 1) {
            int y = __shfl_up_sync(FULL, s, off);
            if (lane >= off) s += y;
        }
        warpsums[lane] = s;
    }
    __syncthreads();
    int base = (wid > 0) ? warpsums[wid - 1] : 0;
    return base + x - v;
}

__global__ void k_scan_a() {
    __shared__ int ws[32];
    int i = blockIdx.x * SCAN_T + threadIdx.x;
    int v = (i < NN) ? g_cnt[i] : 0;
    int ex = block_excl_scan(v, ws);
    if (i < NN) g_rowstart[i] = ex;
    if (threadIdx.x == SCAN_T - 1) g_part[blockIdx.x] = ex + v;
}

__global__ void k_scan_c() {
    __shared__ int parts[NB];
    if (threadIdx.x < NB) parts[threadIdx.x] = g_part[threadIdx.x];
    __syncthreads();
    int pre = 0;
    for (int j = 0; j < NB; j++)
        if (j < blockIdx.x) pre += parts[j];
    int i = blockIdx.x * SCAN_T + threadIdx.x;
    if (i < NN) {
        int r = g_rowstart[i] + pre;
        g_rowstart[i] = r;
        g_cursor[i] = r;
    }
    if (i == 0) g_rowstart[NN] = EE;
}

__global__ void k_fill(const int* __restrict__ ei) {
    int e = blockIdx.x * blockDim.x + threadIdx.x;
    if (e >= EE) return;
    int s = ei[e], d = ei[EE + e];
    int pos = atomicAdd(&g_cursor[d], 1);
    g_csr[pos] = s;
}

// ---------------------------------------------------------------------------
__device__ __forceinline__ void acc_h(int s, int lane, float ex,
                                      float& a0, float& a1, float& a2, float& a3) {
    uint2 u = *(const uint2*)&g_hh[s * 64 + lane * 2];
    float2 f0 = __half22float2(*reinterpret_cast<__half2*>(&u.x));
    float2 f1 = __half22float2(*reinterpret_cast<__half2*>(&u.y));
    a0 += ex * f0.x; a1 += ex * f0.y; a2 += ex * f1.x; a3 += ex * f1.y;
}

__global__ void __launch_bounds__(256)
k_gather(const float* __restrict__ bias,
         const float* __restrict__ gamma,
         const float* __restrict__ beta,
         float* __restrict__ out) {
    int t = blockIdx.x * blockDim.x + threadIdx.x;
    int n = t >> 5, lane = t & 31;
    if (n >= NN) return;
    int head = lane >> 2;

    float adn = g_adst[n * HH + head];
    float a0 = 0.f, a1 = 0.f, a2 = 0.f, a3 = 0.f, den = 0.f;

    {   // self-loop
        float e = g_asrc[n * HH + head] + adn;
        e = e > 0.f ? e : NEG * e;
        float ex = __expf(e);
        acc_h(n, lane, ex, a0, a1, a2, a3);
        den += ex;
    }

    int start = g_rowstart[n], end = g_rowstart[n + 1];
    for (int base = start; base < end; base += 32) {
        int j = base + lane;
        int sj = (j < end) ? g_csr[j] : 0;
        int m = min(32, end - base);
        int k = 0;
        for (; k + 4 <= m; k += 4) {
            int s0 = __shfl_sync(FULL, sj, k);
            int s1 = __shfl_sync(FULL, sj, k + 1);
            int s2 = __shfl_sync(FULL, sj, k + 2);
            int s3 = __shfl_sync(FULL, sj, k + 3);
            float e0 = g_asrc[s0 * HH + head] + adn;
            float e1 = g_asrc[s1 * HH + head] + adn;
            float e2 = g_asrc[s2 * HH + head] + adn;
            float e3 = g_asrc[s3 * HH + head] + adn;
            e0 = e0 > 0.f ? e0 : NEG * e0;
            e1 = e1 > 0.f ? e1 : NEG * e1;
            e2 = e2 > 0.f ? e2 : NEG * e2;
            e3 = e3 > 0.f ? e3 : NEG * e3;
            float x0 = __expf(e0), x1 = __expf(e1);
            float x2 = __expf(e2), x3 = __expf(e3);
            acc_h(s0, lane, x0, a0, a1, a2, a3);
            acc_h(s1, lane, x1, a0, a1, a2, a3);
            acc_h(s2, lane, x2, a0, a1, a2, a3);
            acc_h(s3, lane, x3, a0, a1, a2, a3);
            den += x0 + x1 + x2 + x3;
        }
        for (; k < m; k++) {
            int s = __shfl_sync(FULL, sj, k);
            float e = g_asrc[s * HH + head] + adn;
            e = e > 0.f ? e : NEG * e;
            float ex = __expf(e);
            acc_h(s, lane, ex, a0, a1, a2, a3);
            den += ex;
        }
    }

    float inv = 1.0f / den;
    uint2 us = *(const uint2*)&g_sk[n * 64 + lane * 2];
    float2 s0 = __half22float2(*reinterpret_cast<__half2*>(&us.x));
    float2 s1 = __half22float2(*reinterpret_cast<__half2*>(&us.y));
    float4 b  = *(const float4*)&bias[lane * 4];
    float z0 = a0 * inv + b.x + 0.1f * s0.x;
    float z1 = a1 * inv + b.y + 0.1f * s0.y;
    float z2 = a2 * inv + b.z + 0.1f * s1.x;
    float z3 = a3 * inv + b.w + 0.1f * s1.y;

    float sum = z0 + z1 + z2 + z3;
    float sq  = z0 * z0 + z1 * z1 + z2 * z2 + z3 * z3;
#pragma unroll
    for (int off = 16; off >= 1; off >>= 1) {
        sum += __shfl_xor_sync(FULL, sum, off);
        sq  += __shfl_xor_sync(FULL, sq, off);
    }
    float mu   = sum * (1.0f / 128.0f);
    float var  = sq * (1.0f / 128.0f) - mu * mu;
    float rstd = rsqrtf(var + 1e-5f);
    float4 g  = *(const float4*)&gamma[lane * 4];
    float4 be = *(const float4*)&beta[lane * 4];
    float y0 = (z0 - mu) * rstd * g.x + be.x;
    float y1 = (z1 - mu) * rstd * g.y + be.y;
    float y2 = (z2 - mu) * rstd * g.z + be.z;
    float y3 = (z3 - mu) * rstd * g.w + be.w;
    y0 = y0 > 0.f ? y0 : expm1f(y0);
    y1 = y1 > 0.f ? y1 : expm1f(y1);
    y2 = y2 > 0.f ? y2 : expm1f(y2);
    y3 = y3 > 0.f ? y3 : expm1f(y3);
    *(float4*)&out[n * HC + lane * 4] = make_float4(y0, y1, y2, y3);
}

// ---------------------------------------------------------------------------
extern "C" void kernel_launch(void* const* d_in, const int* in_sizes, int n_in,
                              void* d_out, int out_size) {
    const float* x       = (const float*)d_in[0];
    const int*   ei      = (const int*)d_in[1];
    const float* W_gat   = (const float*)d_in[2];
    const float* att_src = (const float*)d_in[3];
    const float* att_dst = (const float*)d_in[4];
    const float* bias    = (const float*)d_in[5];
    const float* W_skip  = (const float*)d_in[6];
    const float* gamma   = (const float*)d_in[7];
    const float* beta    = (const float*)d_in[8];
    float* out = (float*)d_out;

    k_zero<<<(NN + 255) / 256, 256>>>();
    k_prep<<<(NN * 32 + 255) / 256, 256>>>(x);
    k_prepw<<<(256 * 96 + 255) / 256, 256>>>(W_gat, W_skip);
    k_mm<<<dim3((NN + 127) / 128, 2), 256>>>(att_src, att_dst);
    k_hist<<<(EE + 255) / 256, 256>>>(ei);
    k_scan_a<<<NB, SCAN_T>>>();
    k_scan_c<<<NB, SCAN_T>>>();
    k_fill<<<(EE + 255) / 256, 256>>>(ei);
    k_gather<<<(NN * 32 + 255) / 256, 256>>>(bias, gamma, beta, out);
}

// round 7
// speedup vs baseline: 1.9497x; 1.0969x over previous
#include <cuda_runtime.h>
#include <cuda_fp16.h>
#include <cuda_bf16.h>

#define NN 50000
#define EE 800000
#define HH 8
#define HC 128
#define NEG 0.2f
#define FULL 0xffffffffu

#define SCAN_T 1024
#define NB ((NN + SCAN_T - 1) / SCAN_T)   // 49

// Scratch (device globals; no cudaMalloc anywhere)
__device__ __nv_bfloat16 g_xs[NN * 384];   // [Xhi | Xhi | Xlo] per row
__device__ __nv_bfloat16 g_wc[256 * 384];  // W^T: row n, k-cols [Whi | Wlo | Whi]
__device__ __half2 g_hh[NN * 64];          // h  (fp16 messages)
__device__ __half2 g_sk[NN * 64];          // skip (fp16)
__device__ float   g_asrc[NN * HH];
__device__ float   g_adst[NN * HH];
__device__ int     g_cnt[NN];
__device__ int     g_rowstart[NN + 1];
__device__ int     g_cursor[NN];
__device__ int     g_part[NB];
__device__ int     g_csr[EE];

// ---------------------------------------------------------------------------
__global__ void k_zero() {
    int i = blockIdx.x * blockDim.x + threadIdx.x;
    if (i < NN) g_cnt[i] = 0;
}

// ---------------------------------------------------------------------------
// Split X into bf16 hi/lo: g_xs[n] = [hi(0:128) | hi(128:256) | lo(256:384)]
__global__ void k_prep(const float* __restrict__ X) {
    int t = blockIdx.x * blockDim.x + threadIdx.x;
    int n = t >> 5, c4 = (t & 31) * 4;
    if (n >= NN) return;
    float4 v = *(const float4*)&X[n * 128 + c4];
    __nv_bfloat16 h0 = __float2bfloat16_rn(v.x);
    __nv_bfloat16 h1 = __float2bfloat16_rn(v.y);
    __nv_bfloat16 h2 = __float2bfloat16_rn(v.z);
    __nv_bfloat16 h3 = __float2bfloat16_rn(v.w);
    __nv_bfloat16 l0 = __float2bfloat16_rn(v.x - __bfloat162float(h0));
    __nv_bfloat16 l1 = __float2bfloat16_rn(v.y - __bfloat162float(h1));
    __nv_bfloat16 l2 = __float2bfloat16_rn(v.z - __bfloat162float(h2));
    __nv_bfloat16 l3 = __float2bfloat16_rn(v.w - __bfloat162float(h3));
    __nv_bfloat16 hi4[4] = {h0, h1, h2, h3};
    __nv_bfloat16 lo4[4] = {l0, l1, l2, l3};
    long base = (long)n * 384;
    *(uint2*)&g_xs[base + c4]       = *(uint2*)hi4;
    *(uint2*)&g_xs[base + 128 + c4] = *(uint2*)hi4;
    *(uint2*)&g_xs[base + 256 + c4] = *(uint2*)lo4;
}

// Build transposed split weights: g_wc[n][k], n in 0..255 (gat|skip),
// k 0-127 = hi(W[k][n]), 128-255 = lo, 256-383 = hi.
__global__ void k_prepw(const float* __restrict__ Wg, const float* __restrict__ Ws) {
    int t = blockIdx.x * blockDim.x + threadIdx.x;  // 256*96 groups of 4
    if (t >= 256 * 96) return;
    int n = t / 96, kq = t % 96;
    int k0 = kq * 4;
    __nv_bfloat16 out4[4];
#pragma unroll
    for (int j = 0; j < 4; j++) {
        int k = k0 + j;
        int kk = k & 127;
        float w = (n < 128) ? Wg[kk * 128 + n] : Ws[kk * 128 + n - 128];
        __nv_bfloat16 hi = __float2bfloat16_rn(w);
        if (k >= 128 && k < 256) {
            out4[j] = __float2bfloat16_rn(w - __bfloat162float(hi));
        } else {
            out4[j] = hi;
        }
    }
    *(uint2*)&g_wc[n * 384 + k0] = *(uint2*)out4;
}

// ---------------------------------------------------------------------------
// Tensor-core GEMM with cp.async double-buffer + ldmatrix fragments.
// C[m,n] = sum_k g_xs[m,k] * g_wc[n,k]  (K=384 bf16, fp32 acc)
// grid.y = 0 -> h + attention dots, 1 -> skip.
// Block: 256 thr = 8 warps, warp grid 4(M)x2(N), warp tile 32x64.
#define KCH 32
#define NCH 12
#define LDA 40

__device__ __forceinline__ void ldsm_x4(unsigned& r0, unsigned& r1,
                                        unsigned& r2, unsigned& r3, unsigned addr) {
    asm volatile("ldmatrix.sync.aligned.m8n8.x4.shared.b16 {%0,%1,%2,%3}, [%4];"
                 : "=r"(r0), "=r"(r1), "=r"(r2), "=r"(r3) : "r"(addr));
}

__global__ void __launch_bounds__(256)
k_mm(const float* __restrict__ att_s, const float* __restrict__ att_d) {
    __shared__ __nv_bfloat16 As[2][128 * LDA];
    __shared__ __nv_bfloat16 Bs[2][128 * LDA];
    int tid = threadIdx.x;
    int wid = tid >> 5, lane = tid & 31;
    int g = lane >> 2, t = lane & 3;
    int m0 = blockIdx.x * 128;
    int gy = blockIdx.y;
    int wrow = (wid >> 1) * 32, wcol = (wid & 1) * 64;

    unsigned as_base = (unsigned)__cvta_generic_to_shared(&As[0][0]);
    unsigned bs_base = (unsigned)__cvta_generic_to_shared(&Bs[0][0]);
    const unsigned buf_bytes = 128 * LDA * 2;

    // per-thread cp.async source/dest offsets (2 chunks of 16B each for A and B)
    int r0i = tid >> 2, c8 = (tid & 3) * 8;            // idx = tid
    int r1i = (tid + 256) >> 2;                        // idx = tid + 256 (same c8)
    int gmA0 = m0 + r0i, gmA1 = m0 + r1i;
    const __nv_bfloat16* wrow0 = &g_wc[(gy * 128 + r0i) * 384 + c8];
    const __nv_bfloat16* wrow1 = &g_wc[(gy * 128 + r1i) * 384 + c8];
    const __nv_bfloat16* xrow0 = &g_xs[(long)min(gmA0, NN - 1) * 384 + c8];
    const __nv_bfloat16* xrow1 = &g_xs[(long)min(gmA1, NN - 1) * 384 + c8];
    int szA0 = (gmA0 < NN) ? 16 : 0;
    int szA1 = (gmA1 < NN) ? 16 : 0;
    unsigned dA0 = as_base + (r0i * LDA + c8) * 2;
    unsigned dA1 = as_base + (r1i * LDA + c8) * 2;
    unsigned dB0 = bs_base + (r0i * LDA + c8) * 2;
    unsigned dB1 = bs_base + (r1i * LDA + c8) * 2;

#define PREFETCH(ch) do {                                                     \
        int _kb = (ch) * KCH;                                                 \
        unsigned _o = ((ch) & 1) * buf_bytes;                                 \
        asm volatile("cp.async.ca.shared.global [%0], [%1], 16, %2;"          \
                     :: "r"(dA0 + _o), "l"(xrow0 + _kb), "r"(szA0));          \
        asm volatile("cp.async.ca.shared.global [%0], [%1], 16, %2;"          \
                     :: "r"(dA1 + _o), "l"(xrow1 + _kb), "r"(szA1));          \
        asm volatile("cp.async.ca.shared.global [%0], [%1], 16;"              \
                     :: "r"(dB0 + _o), "l"(wrow0 + _kb));                     \
        asm volatile("cp.async.ca.shared.global [%0], [%1], 16;"              \
                     :: "r"(dB1 + _o), "l"(wrow1 + _kb));                     \
        asm volatile("cp.async.commit_group;");                               \
    } while (0)

    float d[2][8][4];
#pragma unroll
    for (int mi = 0; mi < 2; mi++)
#pragma unroll
        for (int ni = 0; ni < 8; ni++)
#pragma unroll
            for (int j = 0; j < 4; j++) d[mi][ni][j] = 0.f;

    // ldmatrix lane address components (element offsets, within a buffer)
    int a_row = (lane & 15), a_kof = (lane >> 4) * 8;
    int b_row = (lane & 7) + ((lane >> 4) << 3), b_kof = ((lane >> 3) & 1) * 8;

    PREFETCH(0);

    for (int c = 0; c < NCH; c++) {
        if (c + 1 < NCH) {
            PREFETCH(c + 1);
            asm volatile("cp.async.wait_group 1;");
        } else {
            asm volatile("cp.async.wait_group 0;");
        }
        __syncthreads();
        unsigned abuf = as_base + (c & 1) * buf_bytes;
        unsigned bbuf = bs_base + (c & 1) * buf_bytes;
#pragma unroll
        for (int kk = 0; kk < KCH; kk += 16) {
            unsigned a[2][4], b[8][2];
#pragma unroll
            for (int mi = 0; mi < 2; mi++) {
                int rb = wrow + 16 * mi;
                unsigned ad = abuf + ((rb + a_row) * LDA + kk + a_kof) * 2;
                ldsm_x4(a[mi][0], a[mi][1], a[mi][2], a[mi][3], ad);
            }
#pragma unroll
            for (int bi = 0; bi < 4; bi++) {
                int nb = wcol + 16 * bi + b_row;
                unsigned bd = bbuf + (nb * LDA + kk + b_kof) * 2;
                ldsm_x4(b[2 * bi][0], b[2 * bi][1], b[2 * bi + 1][0], b[2 * bi + 1][1], bd);
            }
#pragma unroll
            for (int mi = 0; mi < 2; mi++)
#pragma unroll
                for (int ni = 0; ni < 8; ni++) {
                    asm volatile(
                        "mma.sync.aligned.m16n8k16.row.col.f32.bf16.bf16.f32 "
                        "{%0,%1,%2,%3}, {%4,%5,%6,%7}, {%8,%9}, {%0,%1,%2,%3};\n"
                        : "+f"(d[mi][ni][0]), "+f"(d[mi][ni][1]),
                          "+f"(d[mi][ni][2]), "+f"(d[mi][ni][3])
                        : "r"(a[mi][0]), "r"(a[mi][1]), "r"(a[mi][2]), "r"(a[mi][3]),
                          "r"(b[ni][0]), "r"(b[ni][1]));
                }
        }
        __syncthreads();
    }

    // Epilogue. Lane owns rows r0 = base+g, r1 = r0+8 and cols c0=wcol+8ni+2t, c0+1.
    __half2* dstp = (gy == 0) ? g_hh : g_sk;
#pragma unroll
    for (int mi = 0; mi < 2; mi++) {
        int r0 = m0 + wrow + 16 * mi + g;
        int r1 = r0 + 8;
#pragma unroll
        for (int ni = 0; ni < 8; ni++) {
            int pidx = wcol / 2 + 4 * ni + t;   // half2 index (col/2)
            if (r0 < NN) dstp[r0 * 64 + pidx] = __floats2half2_rn(d[mi][ni][0], d[mi][ni][1]);
            if (r1 < NN) dstp[r1 * 64 + pidx] = __floats2half2_rn(d[mi][ni][2], d[mi][ni][3]);
        }
        if (gy == 0) {
            // attention dots: 4 heads per warp-half (head = wcol/16 + lh)
#pragma unroll
            for (int lh = 0; lh < 4; lh++) {
                float ps0 = 0.f, pd0 = 0.f, ps1 = 0.f, pd1 = 0.f;
#pragma unroll
                for (int j = 0; j < 2; j++) {
                    int ni = 2 * lh + j;
                    int c0 = wcol + 8 * ni + 2 * t;
                    float as0 = att_s[c0], as1 = att_s[c0 + 1];
                    float ad0 = att_d[c0], ad1 = att_d[c0 + 1];
                    ps0 += d[mi][ni][0] * as0 + d[mi][ni][1] * as1;
                    pd0 += d[mi][ni][0] * ad0 + d[mi][ni][1] * ad1;
                    ps1 += d[mi][ni][2] * as0 + d[mi][ni][3] * as1;
                    pd1 += d[mi][ni][2] * ad0 + d[mi][ni][3] * ad1;
                }
                ps0 += __shfl_xor_sync(FULL, ps0, 1); ps0 += __shfl_xor_sync(FULL, ps0, 2);
                pd0 += __shfl_xor_sync(FULL, pd0, 1); pd0 += __shfl_xor_sync(FULL, pd0, 2);
                ps1 += __shfl_xor_sync(FULL, ps1, 1); ps1 += __shfl_xor_sync(FULL, ps1, 2);
                pd1 += __shfl_xor_sync(FULL, pd1, 1); pd1 += __shfl_xor_sync(FULL, pd1, 2);
                int head = wcol / 16 + lh;
                if (t == 0) {
                    if (r0 < NN) { g_asrc[r0 * HH + head] = ps0; g_adst[r0 * HH + head] = pd0; }
                    if (r1 < NN) { g_asrc[r1 * HH + head] = ps1; g_adst[r1 * HH + head] = pd1; }
                }
            }
        }
    }
}

// ---------------------------------------------------------------------------
__global__ void k_hist(const int* __restrict__ ei) {
    int e = blockIdx.x * blockDim.x + threadIdx.x;
    if (e < EE) atomicAdd(&g_cnt[ei[EE + e]], 1);
}

__device__ __forceinline__ int block_excl_scan(int v, int* warpsums) {
    int lane = threadIdx.x & 31, wid = threadIdx.x >> 5;
    int x = v;
#pragma unroll
    for (int off = 1; off < 32; off <<= 1) {
        int y = __shfl_up_sync(FULL, x, off);
        if (lane >= off) x += y;
    }
    if (lane == 31) warpsums[wid] = x;
    __syncthreads();
    if (wid == 0) {
        int nw = (blockDim.x + 31) >> 5;
        int s = (lane < nw) ? warpsums[lane] : 0;
#pragma unroll
        for (int off = 1; off < 32; off <<= 1) {
            int y = __shfl_up_sync(FULL, s, off);
            if (lane >= off) s += y;
        }
        warpsums[lane] = s;
    }
    __syncthreads();
    int base = (wid > 0) ? warpsums[wid - 1] : 0;
    return base + x - v;
}

__global__ void k_scan_a() {
    __shared__ int ws[32];
    int i = blockIdx.x * SCAN_T + threadIdx.x;
    int v = (i < NN) ? g_cnt[i] : 0;
    int ex = block_excl_scan(v, ws);
    if (i < NN) g_rowstart[i] = ex;
    if (threadIdx.x == SCAN_T - 1) g_part[blockIdx.x] = ex + v;
}

__global__ void k_scan_c() {
    __shared__ int parts[NB];
    if (threadIdx.x < NB) parts[threadIdx.x] = g_part[threadIdx.x];
    __syncthreads();
    int pre = 0;
    for (int j = 0; j < NB; j++)
        if (j < blockIdx.x) pre += parts[j];
    int i = blockIdx.x * SCAN_T + threadIdx.x;
    if (i < NN) {
        int r = g_rowstart[i] + pre;
        g_rowstart[i] = r;
        g_cursor[i] = r;
    }
    if (i == 0) g_rowstart[NN] = EE;
}

__global__ void k_fill(const int* __restrict__ ei) {
    int e = blockIdx.x * blockDim.x + threadIdx.x;
    if (e >= EE) return;
    int s = ei[e], d = ei[EE + e];
    int pos = atomicAdd(&g_cursor[d], 1);
    g_csr[pos] = s;
}

// ---------------------------------------------------------------------------
__device__ __forceinline__ void acc_h(int s, int lane, float ex,
                                      float& a0, float& a1, float& a2, float& a3) {
    uint2 u = *(const uint2*)&g_hh[s * 64 + lane * 2];
    float2 f0 = __half22float2(*reinterpret_cast<__half2*>(&u.x));
    float2 f1 = __half22float2(*reinterpret_cast<__half2*>(&u.y));
    a0 += ex * f0.x; a1 += ex * f0.y; a2 += ex * f1.x; a3 += ex * f1.y;
}

__global__ void __launch_bounds__(256)
k_gather(const float* __restrict__ bias,
         const float* __restrict__ gamma,
         const float* __restrict__ beta,
         float* __restrict__ out) {
    int t = blockIdx.x * blockDim.x + threadIdx.x;
    int n = t >> 5, lane = t & 31;
    if (n >= NN) return;
    int head = lane >> 2;

    float adn = g_adst[n * HH + head];
    float a0 = 0.f, a1 = 0.f, a2 = 0.f, a3 = 0.f, den = 0.f;

    {   // self-loop
        float e = g_asrc[n * HH + head] + adn;
        e = e > 0.f ? e : NEG * e;
        float ex = __expf(e);
        acc_h(n, lane, ex, a0, a1, a2, a3);
        den += ex;
    }

    int start = g_rowstart[n], end = g_rowstart[n + 1];
    for (int base = start; base < end; base += 32) {
        int j = base + lane;
        int sj = (j < end) ? g_csr[j] : 0;
        int m = min(32, end - base);
        int k = 0;
        for (; k + 4 <= m; k += 4) {
            int s0 = __shfl_sync(FULL, sj, k);
            int s1 = __shfl_sync(FULL, sj, k + 1);
            int s2 = __shfl_sync(FULL, sj, k + 2);
            int s3 = __shfl_sync(FULL, sj, k + 3);
            float e0 = g_asrc[s0 * HH + head] + adn;
            float e1 = g_asrc[s1 * HH + head] + adn;
            float e2 = g_asrc[s2 * HH + head] + adn;
            float e3 = g_asrc[s3 * HH + head] + adn;
            e0 = e0 > 0.f ? e0 : NEG * e0;
            e1 = e1 > 0.f ? e1 : NEG * e1;
            e2 = e2 > 0.f ? e2 : NEG * e2;
            e3 = e3 > 0.f ? e3 : NEG * e3;
            float x0 = __expf(e0), x1 = __expf(e1);
            float x2 = __expf(e2), x3 = __expf(e3);
            acc_h(s0, lane, x0, a0, a1, a2, a3);
            acc_h(s1, lane, x1, a0, a1, a2, a3);
            acc_h(s2, lane, x2, a0, a1, a2, a3);
            acc_h(s3, lane, x3, a0, a1, a2, a3);
            den += x0 + x1 + x2 + x3;
        }
        for (; k < m; k++) {
            int s = __shfl_sync(FULL, sj, k);
            float e = g_asrc[s * HH + head] + adn;
            e = e > 0.f ? e : NEG * e;
            float ex = __expf(e);
            acc_h(s, lane, ex, a0, a1, a2, a3);
            den += ex;
        }
    }

    float inv = 1.0f / den;
    uint2 us = *(const uint2*)&g_sk[n * 64 + lane * 2];
    float2 s0 = __half22float2(*reinterpret_cast<__half2*>(&us.x));
    float2 s1 = __half22float2(*reinterpret_cast<__half2*>(&us.y));
    float4 b  = *(const float4*)&bias[lane * 4];
    float z0 = a0 * inv + b.x + 0.1f * s0.x;
    float z1 = a1 * inv + b.y + 0.1f * s0.y;
    float z2 = a2 * inv + b.z + 0.1f * s1.x;
    float z3 = a3 * inv + b.w + 0.1f * s1.y;

    float sum = z0 + z1 + z2 + z3;
    float sq  = z0 * z0 + z1 * z1 + z2 * z2 + z3 * z3;
#pragma unroll
    for (int off = 16; off >= 1; off >>= 1) {
        sum += __shfl_xor_sync(FULL, sum, off);
        sq  += __shfl_xor_sync(FULL, sq, off);
    }
    float mu   = sum * (1.0f / 128.0f);
    float var  = sq * (1.0f / 128.0f) - mu * mu;
    float rstd = rsqrtf(var + 1e-5f);
    float4 g  = *(const float4*)&gamma[lane * 4];
    float4 be = *(const float4*)&beta[lane * 4];
    float y0 = (z0 - mu) * rstd * g.x + be.x;
    float y1 = (z1 - mu) * rstd * g.y + be.y;
    float y2 = (z2 - mu) * rstd * g.z + be.z;
    float y3 = (z3 - mu) * rstd * g.w + be.w;
    y0 = y0 > 0.f ? y0 : expm1f(y0);
    y1 = y1 > 0.f ? y1 : expm1f(y1);
    y2 = y2 > 0.f ? y2 : expm1f(y2);
    y3 = y3 > 0.f ? y3 : expm1f(y3);
    *(float4*)&out[n * HC + lane * 4] = make_float4(y0, y1, y2, y3);
}

// ---------------------------------------------------------------------------
extern "C" void kernel_launch(void* const* d_in, const int* in_sizes, int n_in,
                              void* d_out, int out_size) {
    const float* x       = (const float*)d_in[0];
    const int*   ei      = (const int*)d_in[1];
    const float* W_gat   = (const float*)d_in[2];
    const float* att_src = (const float*)d_in[3];
    const float* att_dst = (const float*)d_in[4];
    const float* bias    = (const float*)d_in[5];
    const float* W_skip  = (const float*)d_in[6];
    const float* gamma   = (const float*)d_in[7];
    const float* beta    = (const float*)d_in[8];
    float* out = (float*)d_out;

    k_zero<<<(NN + 255) / 256, 256>>>();
    k_prep<<<(NN * 32 + 255) / 256, 256>>>(x);
    k_prepw<<<(256 * 96 + 255) / 256, 256>>>(W_gat, W_skip);
    k_mm<<<dim3((NN + 127) / 128, 2), 256>>>(att_src, att_dst);
    k_hist<<<(EE + 255) / 256, 256>>>(ei);
    k_scan_a<<<NB, SCAN_T>>>();
    k_scan_c<<<NB, SCAN_T>>>();
    k_fill<<<(EE + 255) / 256, 256>>>(ei);
    k_gather<<<(NN * 32 + 255) / 256, 256>>>(bias, gamma, beta, out);
}

// round 8
// speedup vs baseline: 1.9502x; 1.0002x over previous
#include <cuda_runtime.h>
#include <cuda_fp16.h>
#include <cuda_bf16.h>

#define NN 50000
#define EE 800000
#define HH 8
#define HC 128
#define NEG 0.2f
#define FULL 0xffffffffu

#define SCAN_T 1024
#define NB ((NN + SCAN_T - 1) / SCAN_T)   // 49

// Scratch (device globals; no cudaMalloc anywhere)
__device__ __nv_bfloat16 g_xs[NN * 256];   // [Xhi | Xlo] per row
__device__ __nv_bfloat16 g_wc[256 * 384];  // W^T: row n, k-cols [Whi | Wlo | Whi]
__device__ __half2 g_hh[NN * 64];          // h  (fp16 messages)
__device__ __half2 g_sk[NN * 64];          // skip (fp16)
__device__ float   g_asrc[NN * HH];
__device__ float   g_adst[NN * HH];
__device__ int     g_cnt[NN];
__device__ int     g_rowstart[NN + 1];
__device__ int     g_cursor[NN];
__device__ int     g_part[NB];
__device__ int     g_csr[EE];

// ---------------------------------------------------------------------------
__global__ void k_zero() {
    int i = blockIdx.x * blockDim.x + threadIdx.x;
    if (i < NN) g_cnt[i] = 0;
}

// ---------------------------------------------------------------------------
// Split X into bf16 hi/lo: g_xs[n] = [hi(0:128) | lo(128:256)]
__global__ void k_prep(const float* __restrict__ X) {
    int t = blockIdx.x * blockDim.x + threadIdx.x;
    int n = t >> 5, c4 = (t & 31) * 4;
    if (n >= NN) return;
    float4 v = *(const float4*)&X[n * 128 + c4];
    __nv_bfloat16 h0 = __float2bfloat16_rn(v.x);
    __nv_bfloat16 h1 = __float2bfloat16_rn(v.y);
    __nv_bfloat16 h2 = __float2bfloat16_rn(v.z);
    __nv_bfloat16 h3 = __float2bfloat16_rn(v.w);
    __nv_bfloat16 l0 = __float2bfloat16_rn(v.x - __bfloat162float(h0));
    __nv_bfloat16 l1 = __float2bfloat16_rn(v.y - __bfloat162float(h1));
    __nv_bfloat16 l2 = __float2bfloat16_rn(v.z - __bfloat162float(h2));
    __nv_bfloat16 l3 = __float2bfloat16_rn(v.w - __bfloat162float(h3));
    __nv_bfloat16 hi4[4] = {h0, h1, h2, h3};
    __nv_bfloat16 lo4[4] = {l0, l1, l2, l3};
    long base = (long)n * 256;
    *(uint2*)&g_xs[base + c4]       = *(uint2*)hi4;
    *(uint2*)&g_xs[base + 128 + c4] = *(uint2*)lo4;
}

// Build transposed split weights: g_wc[n][k], n in 0..255 (gat|skip),
// k 0-127 = hi(W[k][n]), 128-255 = lo, 256-383 = hi (dup).
__global__ void k_prepw(const float* __restrict__ Wg, const float* __restrict__ Ws) {
    int t = blockIdx.x * blockDim.x + threadIdx.x;  // 256*96 groups of 4
    if (t >= 256 * 96) return;
    int n = t / 96, kq = t % 96;
    int k0 = kq * 4;
    __nv_bfloat16 out4[4];
#pragma unroll
    for (int j = 0; j < 4; j++) {
        int k = k0 + j;
        int kk = k & 127;
        float w = (n < 128) ? Wg[kk * 128 + n] : Ws[kk * 128 + n - 128];
        __nv_bfloat16 hi = __float2bfloat16_rn(w);
        if (k >= 128 && k < 256) {
            out4[j] = __float2bfloat16_rn(w - __bfloat162float(hi));
        } else {
            out4[j] = hi;
        }
    }
    *(uint2*)&g_wc[n * 384 + k0] = *(uint2*)out4;
}

// ---------------------------------------------------------------------------
// Tensor-core GEMM, 3-stage cp.async pipeline + ldmatrix fragments.
// Virtual K=384: B chunk c pairs with A chunk (c<4 ? c : c-4) of [Xhi|Xlo].
// grid.y = 0 -> h + attention dots, 1 -> skip.
// Block: 256 thr = 8 warps, warp grid 4(M)x2(N), warp tile 32x64.
#define KCH 32
#define NCH 12
#define LDA 40
#define ABUF (128 * LDA)                 // halves per stage buffer
#define SMEM_MM (6 * ABUF * 2)           // 3 stages x (A+B) bytes = 61440

__device__ __forceinline__ void ldsm_x4(unsigned& r0, unsigned& r1,
                                        unsigned& r2, unsigned& r3, unsigned addr) {
    asm volatile("ldmatrix.sync.aligned.m8n8.x4.shared.b16 {%0,%1,%2,%3}, [%4];"
                 : "=r"(r0), "=r"(r1), "=r"(r2), "=r"(r3) : "r"(addr));
}

__global__ void __launch_bounds__(256)
k_mm(const float* __restrict__ att_s, const float* __restrict__ att_d) {
    extern __shared__ __nv_bfloat16 smem[];
    // layout: A stages at 0,1,2 ; B stages at 3,4,5 (units of ABUF)
    int tid = threadIdx.x;
    int wid = tid >> 5, lane = tid & 31;
    int g = lane >> 2, t = lane & 3;
    int m0 = blockIdx.x * 128;
    int gy = blockIdx.y;
    int wrow = (wid >> 1) * 32, wcol = (wid & 1) * 64;

    unsigned s_base = (unsigned)__cvta_generic_to_shared(&smem[0]);
    const unsigned stage_bytes = ABUF * 2;

    // per-thread cp.async source/dest offsets (2 rows of 16B each for A and B)
    int r0i = tid >> 2, c8 = (tid & 3) * 8;
    int r1i = (tid + 256) >> 2;
    int gmA0 = m0 + r0i, gmA1 = m0 + r1i;
    const __nv_bfloat16* wrow0 = &g_wc[(gy * 128 + r0i) * 384 + c8];
    const __nv_bfloat16* wrow1 = &g_wc[(gy * 128 + r1i) * 384 + c8];
    const __nv_bfloat16* xrow0 = &g_xs[(long)min(gmA0, NN - 1) * 256 + c8];
    const __nv_bfloat16* xrow1 = &g_xs[(long)min(gmA1, NN - 1) * 256 + c8];
    int szA0 = (gmA0 < NN) ? 16 : 0;
    int szA1 = (gmA1 < NN) ? 16 : 0;
    unsigned dA0 = s_base + (r0i * LDA + c8) * 2;
    unsigned dA1 = s_base + (r1i * LDA + c8) * 2;
    unsigned dB0 = s_base + 3 * stage_bytes + (r0i * LDA + c8) * 2;
    unsigned dB1 = s_base + 3 * stage_bytes + (r1i * LDA + c8) * 2;

#define PREFETCH(ch) do {                                                     \
        if ((ch) < NCH) {                                                     \
            int _ach = ((ch) < 4) ? (ch) : (ch) - 4;                          \
            int _ka = _ach * KCH, _kb = (ch) * KCH;                           \
            unsigned _o = ((ch) % 3) * stage_bytes;                           \
            asm volatile("cp.async.ca.shared.global [%0], [%1], 16, %2;"      \
                         :: "r"(dA0 + _o), "l"(xrow0 + _ka), "r"(szA0));      \
            asm volatile("cp.async.ca.shared.global [%0], [%1], 16, %2;"      \
                         :: "r"(dA1 + _o), "l"(xrow1 + _ka), "r"(szA1));      \
            asm volatile("cp.async.ca.shared.global [%0], [%1], 16;"          \
                         :: "r"(dB0 + _o), "l"(wrow0 + _kb));                 \
            asm volatile("cp.async.ca.shared.global [%0], [%1], 16;"          \
                         :: "r"(dB1 + _o), "l"(wrow1 + _kb));                 \
        }                                                                     \
        asm volatile("cp.async.commit_group;");                               \
    } while (0)

    float d[2][8][4];
#pragma unroll
    for (int mi = 0; mi < 2; mi++)
#pragma unroll
        for (int ni = 0; ni < 8; ni++)
#pragma unroll
            for (int j = 0; j < 4; j++) d[mi][ni][j] = 0.f;

    int a_row = (lane & 15), a_kof = (lane >> 4) * 8;
    int b_row = (lane & 7) + ((lane >> 4) << 3), b_kof = ((lane >> 3) & 1) * 8;

    PREFETCH(0);
    PREFETCH(1);

    for (int c = 0; c < NCH; c++) {
        asm volatile("cp.async.wait_group 1;");
        __syncthreads();
        PREFETCH(c + 2);
        unsigned abuf = s_base + (c % 3) * stage_bytes;
        unsigned bbuf = s_base + (3 + c % 3) * stage_bytes;
#pragma unroll
        for (int kk = 0; kk < KCH; kk += 16) {
            unsigned a[2][4], b[8][2];
#pragma unroll
            for (int mi = 0; mi < 2; mi++) {
                int rb = wrow + 16 * mi;
                unsigned ad = abuf + ((rb + a_row) * LDA + kk + a_kof) * 2;
                ldsm_x4(a[mi][0], a[mi][1], a[mi][2], a[mi][3], ad);
            }
#pragma unroll
            for (int bi = 0; bi < 4; bi++) {
                int nb = wcol + 16 * bi + b_row;
                unsigned bd = bbuf + (nb * LDA + kk + b_kof) * 2;
                ldsm_x4(b[2 * bi][0], b[2 * bi][1], b[2 * bi + 1][0], b[2 * bi + 1][1], bd);
            }
#pragma unroll
            for (int mi = 0; mi < 2; mi++)
#pragma unroll
                for (int ni = 0; ni < 8; ni++) {
                    asm volatile(
                        "mma.sync.aligned.m16n8k16.row.col.f32.bf16.bf16.f32 "
                        "{%0,%1,%2,%3}, {%4,%5,%6,%7}, {%8,%9}, {%0,%1,%2,%3};\n"
                        : "+f"(d[mi][ni][0]), "+f"(d[mi][ni][1]),
                          "+f"(d[mi][ni][2]), "+f"(d[mi][ni][3])
                        : "r"(a[mi][0]), "r"(a[mi][1]), "r"(a[mi][2]), "r"(a[mi][3]),
                          "r"(b[ni][0]), "r"(b[ni][1]));
                }
        }
    }

    // Epilogue. Lane owns rows r0 = base+g, r1 = r0+8 and cols c0=wcol+8ni+2t, c0+1.
    __half2* dstp = (gy == 0) ? g_hh : g_sk;
#pragma unroll
    for (int mi = 0; mi < 2; mi++) {
        int r0 = m0 + wrow + 16 * mi + g;
        int r1 = r0 + 8;
#pragma unroll
        for (int ni = 0; ni < 8; ni++) {
            int pidx = wcol / 2 + 4 * ni + t;   // half2 index (col/2)
            if (r0 < NN) dstp[r0 * 64 + pidx] = __floats2half2_rn(d[mi][ni][0], d[mi][ni][1]);
            if (r1 < NN) dstp[r1 * 64 + pidx] = __floats2half2_rn(d[mi][ni][2], d[mi][ni][3]);
        }
        if (gy == 0) {
#pragma unroll
            for (int lh = 0; lh < 4; lh++) {
                float ps0 = 0.f, pd0 = 0.f, ps1 = 0.f, pd1 = 0.f;
#pragma unroll
                for (int j = 0; j < 2; j++) {
                    int ni = 2 * lh + j;
                    int c0 = wcol + 8 * ni + 2 * t;
                    float as0 = att_s[c0], as1 = att_s[c0 + 1];
                    float ad0 = att_d[c0], ad1 = att_d[c0 + 1];
                    ps0 += d[mi][ni][0] * as0 + d[mi][ni][1] * as1;
                    pd0 += d[mi][ni][0] * ad0 + d[mi][ni][1] * ad1;
                    ps1 += d[mi][ni][2] * as0 + d[mi][ni][3] * as1;
                    pd1 += d[mi][ni][2] * ad0 + d[mi][ni][3] * ad1;
                }
                ps0 += __shfl_xor_sync(FULL, ps0, 1); ps0 += __shfl_xor_sync(FULL, ps0, 2);
                pd0 += __shfl_xor_sync(FULL, pd0, 1); pd0 += __shfl_xor_sync(FULL, pd0, 2);
                ps1 += __shfl_xor_sync(FULL, ps1, 1); ps1 += __shfl_xor_sync(FULL, ps1, 2);
                pd1 += __shfl_xor_sync(FULL, pd1, 1); pd1 += __shfl_xor_sync(FULL, pd1, 2);
                int head = wcol / 16 + lh;
                if (t == 0) {
                    if (r0 < NN) { g_asrc[r0 * HH + head] = ps0; g_adst[r0 * HH + head] = pd0; }
                    if (r1 < NN) { g_asrc[r1 * HH + head] = ps1; g_adst[r1 * HH + head] = pd1; }
                }
            }
        }
    }
}

// ---------------------------------------------------------------------------
__global__ void k_hist(const int* __restrict__ ei) {
    int e = blockIdx.x * blockDim.x + threadIdx.x;
    if (e < EE) atomicAdd(&g_cnt[ei[EE + e]], 1);
}

__device__ __forceinline__ int block_excl_scan(int v, int* warpsums) {
    int lane = threadIdx.x & 31, wid = threadIdx.x >> 5;
    int x = v;
#pragma unroll
    for (int off = 1; off < 32; off <<= 1) {
        int y = __shfl_up_sync(FULL, x, off);
        if (lane >= off) x += y;
    }
    if (lane == 31) warpsums[wid] = x;
    __syncthreads();
    if (wid == 0) {
        int nw = (blockDim.x + 31) >> 5;
        int s = (lane < nw) ? warpsums[lane] : 0;
#pragma unroll
        for (int off = 1; off < 32; off <<= 1) {
            int y = __shfl_up_sync(FULL, s, off);
            if (lane >= off) s += y;
        }
        warpsums[lane] = s;
    }
    __syncthreads();
    int base = (wid > 0) ? warpsums[wid - 1] : 0;
    return base + x - v;
}

__global__ void k_scan_a() {
    __shared__ int ws[32];
    int i = blockIdx.x * SCAN_T + threadIdx.x;
    int v = (i < NN) ? g_cnt[i] : 0;
    int ex = block_excl_scan(v, ws);
    if (i < NN) g_rowstart[i] = ex;
    if (threadIdx.x == SCAN_T - 1) g_part[blockIdx.x] = ex + v;
}

__global__ void k_scan_c() {
    __shared__ int parts[NB];
    if (threadIdx.x < NB) parts[threadIdx.x] = g_part[threadIdx.x];
    __syncthreads();
    int pre = 0;
    for (int j = 0; j < NB; j++)
        if (j < blockIdx.x) pre += parts[j];
    int i = blockIdx.x * SCAN_T + threadIdx.x;
    if (i < NN) {
        int r = g_rowstart[i] + pre;
        g_rowstart[i] = r;
        g_cursor[i] = r;
    }
    if (i == 0) g_rowstart[NN] = EE;
}

__global__ void k_fill(const int* __restrict__ ei) {
    int e = blockIdx.x * blockDim.x + threadIdx.x;
    if (e >= EE) return;
    int s = ei[e], d = ei[EE + e];
    int pos = atomicAdd(&g_cursor[d], 1);
    g_csr[pos] = s;
}

// ---------------------------------------------------------------------------
__device__ __forceinline__ void acc_h(int s, int lane, float ex,
                                      float& a0, float& a1, float& a2, float& a3) {
    uint2 u = *(const uint2*)&g_hh[s * 64 + lane * 2];
    float2 f0 = __half22float2(*reinterpret_cast<__half2*>(&u.x));
    float2 f1 = __half22float2(*reinterpret_cast<__half2*>(&u.y));
    a0 += ex * f0.x; a1 += ex * f0.y; a2 += ex * f1.x; a3 += ex * f1.y;
}

__global__ void __launch_bounds__(256)
k_gather(const float* __restrict__ bias,
         const float* __restrict__ gamma,
         const float* __restrict__ beta,
         float* __restrict__ out) {
    int t = blockIdx.x * blockDim.x + threadIdx.x;
    int n = t >> 5, lane = t & 31;
    if (n >= NN) return;
    int head = lane >> 2;

    float adn = g_adst[n * HH + head];
    float a0 = 0.f, a1 = 0.f, a2 = 0.f, a3 = 0.f, den = 0.f;

    {   // self-loop
        float e = g_asrc[n * HH + head] + adn;
        e = e > 0.f ? e : NEG * e;
        float ex = __expf(e);
        acc_h(n, lane, ex, a0, a1, a2, a3);
        den += ex;
    }

    int start = g_rowstart[n], end = g_rowstart[n + 1];
    for (int base = start; base < end; base += 32) {
        int j = base + lane;
        int sj = (j < end) ? g_csr[j] : 0;
        int m = min(32, end - base);
        int k = 0;
        for (; k + 4 <= m; k += 4) {
            int s0 = __shfl_sync(FULL, sj, k);
            int s1 = __shfl_sync(FULL, sj, k + 1);
            int s2 = __shfl_sync(FULL, sj, k + 2);
            int s3 = __shfl_sync(FULL, sj, k + 3);
            float e0 = g_asrc[s0 * HH + head] + adn;
            float e1 = g_asrc[s1 * HH + head] + adn;
            float e2 = g_asrc[s2 * HH + head] + adn;
            float e3 = g_asrc[s3 * HH + head] + adn;
            e0 = e0 > 0.f ? e0 : NEG * e0;
            e1 = e1 > 0.f ? e1 : NEG * e1;
            e2 = e2 > 0.f ? e2 : NEG * e2;
            e3 = e3 > 0.f ? e3 : NEG * e3;
            float x0 = __expf(e0), x1 = __expf(e1);
            float x2 = __expf(e2), x3 = __expf(e3);
            acc_h(s0, lane, x0, a0, a1, a2, a3);
            acc_h(s1, lane, x1, a0, a1, a2, a3);
            acc_h(s2, lane, x2, a0, a1, a2, a3);
            acc_h(s3, lane, x3, a0, a1, a2, a3);
            den += x0 + x1 + x2 + x3;
        }
        for (; k < m; k++) {
            int s = __shfl_sync(FULL, sj, k);
            float e = g_asrc[s * HH + head] + adn;
            e = e > 0.f ? e : NEG * e;
            float ex = __expf(e);
            acc_h(s, lane, ex, a0, a1, a2, a3);
            den += ex;
        }
    }

    float inv = 1.0f / den;
    uint2 us = *(const uint2*)&g_sk[n * 64 + lane * 2];
    float2 s0 = __half22float2(*reinterpret_cast<__half2*>(&us.x));
    float2 s1 = __half22float2(*reinterpret_cast<__half2*>(&us.y));
    float4 b  = *(const float4*)&bias[lane * 4];
    float z0 = a0 * inv + b.x + 0.1f * s0.x;
    float z1 = a1 * inv + b.y + 0.1f * s0.y;
    float z2 = a2 * inv + b.z + 0.1f * s1.x;
    float z3 = a3 * inv + b.w + 0.1f * s1.y;

    float sum = z0 + z1 + z2 + z3;
    float sq  = z0 * z0 + z1 * z1 + z2 * z2 + z3 * z3;
#pragma unroll
    for (int off = 16; off >= 1; off >>= 1) {
        sum += __shfl_xor_sync(FULL, sum, off);
        sq  += __shfl_xor_sync(FULL, sq, off);
    }
    float mu   = sum * (1.0f / 128.0f);
    float var  = sq * (1.0f / 128.0f) - mu * mu;
    float rstd = rsqrtf(var + 1e-5f);
    float4 g  = *(const float4*)&gamma[lane * 4];
    float4 be = *(const float4*)&beta[lane * 4];
    float y0 = (z0 - mu) * rstd * g.x + be.x;
    float y1 = (z1 - mu) * rstd * g.y + be.y;
    float y2 = (z2 - mu) * rstd * g.z + be.z;
    float y3 = (z3 - mu) * rstd * g.w + be.w;
    y0 = y0 > 0.f ? y0 : expm1f(y0);
    y1 = y1 > 0.f ? y1 : expm1f(y1);
    y2 = y2 > 0.f ? y2 : expm1f(y2);
    y3 = y3 > 0.f ? y3 : expm1f(y3);
    *(float4*)&out[n * HC + lane * 4] = make_float4(y0, y1, y2, y3);
}

// ---------------------------------------------------------------------------
extern "C" void kernel_launch(void* const* d_in, const int* in_sizes, int n_in,
                              void* d_out, int out_size) {
    const float* x       = (const float*)d_in[0];
    const int*   ei      = (const int*)d_in[1];
    const float* W_gat   = (const float*)d_in[2];
    const float* att_src = (const float*)d_in[3];
    const float* att_dst = (const float*)d_in[4];
    const float* bias    = (const float*)d_in[5];
    const float* W_skip  = (const float*)d_in[6];
    const float* gamma   = (const float*)d_in[7];
    const float* beta    = (const float*)d_in[8];
    float* out = (float*)d_out;

    cudaFuncSetAttribute(k_mm, cudaFuncAttributeMaxDynamicSharedMemorySize, SMEM_MM);

    k_zero<<<(NN + 255) / 256, 256>>>();
    k_prep<<<(NN * 32 + 255) / 256, 256>>>(x);
    k_prepw<<<(256 * 96 + 255) / 256, 256>>>(W_gat, W_skip);
    k_mm<<<dim3((NN + 127) / 128, 2), 256, SMEM_MM>>>(att_src, att_dst);
    k_hist<<<(EE + 255) / 256, 256>>>(ei);
    k_scan_a<<<NB, SCAN_T>>>();
    k_scan_c<<<NB, SCAN_T>>>();
    k_fill<<<(EE + 255) / 256, 256>>>(ei);
    k_gather<<<(NN * 32 + 255) / 256, 256>>>(bias, gamma, beta, out);
}

// round 10
// speedup vs baseline: 2.1199x; 1.0870x over previous
#include <cuda_runtime.h>
#include <cuda_fp16.h>
#include <cuda_bf16.h>

#define NN 50000
#define EE 800000
#define HH 8
#define HC 128
#define NEG 0.2f
#define FULL 0xffffffffu

#define SCAN_T 1024
#define NB ((NN + SCAN_T - 1) / SCAN_T)   // 49

// Scratch (device globals; no cudaMalloc anywhere)
__device__ __nv_bfloat16 g_xs[NN * 256];   // [Xhi | Xlo] per row
__device__ __nv_bfloat16 g_wc[256 * 384];  // W^T: row n, k-cols [Whi | Wlo | Whi]
__device__ __half2 g_hh[NN * 64];          // h  (fp16 messages)
__device__ __half2 g_sk[NN * 64];          // skip (fp16)
__device__ float   g_asrc[NN * HH];
__device__ float   g_adst[NN * HH];
__device__ int     g_cnt[NN];              // zero at run start (re-zeroed each run)
__device__ int     g_rowstart[NN + 1];
__device__ int     g_cursor[NN];
__device__ int     g_part[NB];
__device__ int     g_csr[EE];

// ---------------------------------------------------------------------------
// Split X into bf16 hi/lo: g_xs[n] = [hi(0:128) | lo(128:256)]
__global__ void k_prep(const float* __restrict__ X) {
    int t = blockIdx.x * blockDim.x + threadIdx.x;
    int n = t >> 5, c4 = (t & 31) * 4;
    if (n >= NN) return;
    float4 v = *(const float4*)&X[n * 128 + c4];
    __nv_bfloat16 h0 = __float2bfloat16_rn(v.x);
    __nv_bfloat16 h1 = __float2bfloat16_rn(v.y);
    __nv_bfloat16 h2 = __float2bfloat16_rn(v.z);
    __nv_bfloat16 h3 = __float2bfloat16_rn(v.w);
    __nv_bfloat16 l0 = __float2bfloat16_rn(v.x - __bfloat162float(h0));
    __nv_bfloat16 l1 = __float2bfloat16_rn(v.y - __bfloat162float(h1));
    __nv_bfloat16 l2 = __float2bfloat16_rn(v.z - __bfloat162float(h2));
    __nv_bfloat16 l3 = __float2bfloat16_rn(v.w - __bfloat162float(h3));
    __nv_bfloat16 hi4[4] = {h0, h1, h2, h3};
    __nv_bfloat16 lo4[4] = {l0, l1, l2, l3};
    long base = (long)n * 256;
    *(uint2*)&g_xs[base + c4]       = *(uint2*)hi4;
    *(uint2*)&g_xs[base + 128 + c4] = *(uint2*)lo4;
}

// Build transposed split weights: g_wc[n][k], n in 0..255 (gat|skip),
// k 0-127 = hi(W[k][n]), 128-255 = lo, 256-383 = hi (dup).
__global__ void k_prepw(const float* __restrict__ Wg, const float* __restrict__ Ws) {
    int t = blockIdx.x * blockDim.x + threadIdx.x;  // 256*96 groups of 4
    if (t >= 256 * 96) return;
    int n = t / 96, kq = t % 96;
    int k0 = kq * 4;
    __nv_bfloat16 out4[4];
#pragma unroll
    for (int j = 0; j < 4; j++) {
        int k = k0 + j;
        int kk = k & 127;
        float w = (n < 128) ? Wg[kk * 128 + n] : Ws[kk * 128 + n - 128];
        __nv_bfloat16 hi = __float2bfloat16_rn(w);
        if (k >= 128 && k < 256) {
            out4[j] = __float2bfloat16_rn(w - __bfloat162float(hi));
        } else {
            out4[j] = hi;
        }
    }
    *(uint2*)&g_wc[n * 384 + k0] = *(uint2*)out4;
}

// ---------------------------------------------------------------------------
// Tensor-core GEMM, 3-stage cp.async pipeline + ldmatrix fragments (R8 proven).
#define KCH 32
#define NCH 12
#define LDA 40
#define ABUF (128 * LDA)
#define SMEM_MM (6 * ABUF * 2)           // 61440 bytes

__device__ __forceinline__ void ldsm_x4(unsigned& r0, unsigned& r1,
                                        unsigned& r2, unsigned& r3, unsigned addr) {
    asm volatile("ldmatrix.sync.aligned.m8n8.x4.shared.b16 {%0,%1,%2,%3}, [%4];"
                 : "=r"(r0), "=r"(r1), "=r"(r2), "=r"(r3) : "r"(addr));
}

__global__ void __launch_bounds__(256)
k_mm(const float* __restrict__ att_s, const float* __restrict__ att_d) {
    extern __shared__ __nv_bfloat16 smem[];
    int tid = threadIdx.x;
    int wid = tid >> 5, lane = tid & 31;
    int g = lane >> 2, t = lane & 3;
    int m0 = blockIdx.x * 128;
    int gy = blockIdx.y;
    int wrow = (wid >> 1) * 32, wcol = (wid & 1) * 64;

    unsigned s_base = (unsigned)__cvta_generic_to_shared(&smem[0]);
    const unsigned stage_bytes = ABUF * 2;

    int r0i = tid >> 2, c8 = (tid & 3) * 8;
    int r1i = (tid + 256) >> 2;
    int gmA0 = m0 + r0i, gmA1 = m0 + r1i;
    const __nv_bfloat16* wrow0 = &g_wc[(gy * 128 + r0i) * 384 + c8];
    const __nv_bfloat16* wrow1 = &g_wc[(gy * 128 + r1i) * 384 + c8];
    const __nv_bfloat16* xrow0 = &g_xs[(long)min(gmA0, NN - 1) * 256 + c8];
    const __nv_bfloat16* xrow1 = &g_xs[(long)min(gmA1, NN - 1) * 256 + c8];
    int szA0 = (gmA0 < NN) ? 16 : 0;
    int szA1 = (gmA1 < NN) ? 16 : 0;
    unsigned dA0 = s_base + (r0i * LDA + c8) * 2;
    unsigned dA1 = s_base + (r1i * LDA + c8) * 2;
    unsigned dB0 = s_base + 3 * stage_bytes + (r0i * LDA + c8) * 2;
    unsigned dB1 = s_base + 3 * stage_bytes + (r1i * LDA + c8) * 2;

#define PREFETCH(ch) do {                                                     \
        if ((ch) < NCH) {                                                     \
            int _ach = ((ch) < 4) ? (ch) : (ch) - 4;                          \
            int _ka = _ach * KCH, _kb = (ch) * KCH;                           \
            unsigned _o = ((ch) % 3) * stage_bytes;                           \
            asm volatile("cp.async.ca.shared.global [%0], [%1], 16, %2;"      \
                         :: "r"(dA0 + _o), "l"(xrow0 + _ka), "r"(szA0));      \
            asm volatile("cp.async.ca.shared.global [%0], [%1], 16, %2;"      \
                         :: "r"(dA1 + _o), "l"(xrow1 + _ka), "r"(szA1));      \
            asm volatile("cp.async.ca.shared.global [%0], [%1], 16;"          \
                         :: "r"(dB0 + _o), "l"(wrow0 + _kb));                 \
            asm volatile("cp.async.ca.shared.global [%0], [%1], 16;"          \
                         :: "r"(dB1 + _o), "l"(wrow1 + _kb));                 \
        }                                                                     \
        asm volatile("cp.async.commit_group;");                               \
    } while (0)

    float d[2][8][4];
#pragma unroll
    for (int mi = 0; mi < 2; mi++)
#pragma unroll
        for (int ni = 0; ni < 8; ni++)
#pragma unroll
            for (int j = 0; j < 4; j++) d[mi][ni][j] = 0.f;

    int a_row = (lane & 15), a_kof = (lane >> 4) * 8;
    int b_row = (lane & 7) + ((lane >> 4) << 3), b_kof = ((lane >> 3) & 1) * 8;

    PREFETCH(0);
    PREFETCH(1);

    for (int c = 0; c < NCH; c++) {
        asm volatile("cp.async.wait_group 1;");
        __syncthreads();
        PREFETCH(c + 2);
        unsigned abuf = s_base + (c % 3) * stage_bytes;
        unsigned bbuf = s_base + (3 + c % 3) * stage_bytes;
#pragma unroll
        for (int kk = 0; kk < KCH; kk += 16) {
            unsigned a[2][4], b[8][2];
#pragma unroll
            for (int mi = 0; mi < 2; mi++) {
                int rb = wrow + 16 * mi;
                unsigned ad = abuf + ((rb + a_row) * LDA + kk + a_kof) * 2;
                ldsm_x4(a[mi][0], a[mi][1], a[mi][2], a[mi][3], ad);
            }
#pragma unroll
            for (int bi = 0; bi < 4; bi++) {
                int nb = wcol + 16 * bi + b_row;
                unsigned bd = bbuf + (nb * LDA + kk + b_kof) * 2;
                ldsm_x4(b[2 * bi][0], b[2 * bi][1], b[2 * bi + 1][0], b[2 * bi + 1][1], bd);
            }
#pragma unroll
            for (int mi = 0; mi < 2; mi++)
#pragma unroll
                for (int ni = 0; ni < 8; ni++) {
                    asm volatile(
                        "mma.sync.aligned.m16n8k16.row.col.f32.bf16.bf16.f32 "
                        "{%0,%1,%2,%3}, {%4,%5,%6,%7}, {%8,%9}, {%0,%1,%2,%3};\n"
                        : "+f"(d[mi][ni][0]), "+f"(d[mi][ni][1]),
                          "+f"(d[mi][ni][2]), "+f"(d[mi][ni][3])
                        : "r"(a[mi][0]), "r"(a[mi][1]), "r"(a[mi][2]), "r"(a[mi][3]),
                          "r"(b[ni][0]), "r"(b[ni][1]));
                }
        }
    }

    __half2* dstp = (gy == 0) ? g_hh : g_sk;
#pragma unroll
    for (int mi = 0; mi < 2; mi++) {
        int r0 = m0 + wrow + 16 * mi + g;
        int r1 = r0 + 8;
#pragma unroll
        for (int ni = 0; ni < 8; ni++) {
            int pidx = wcol / 2 + 4 * ni + t;
            if (r0 < NN) dstp[r0 * 64 + pidx] = __floats2half2_rn(d[mi][ni][0], d[mi][ni][1]);
            if (r1 < NN) dstp[r1 * 64 + pidx] = __floats2half2_rn(d[mi][ni][2], d[mi][ni][3]);
        }
        if (gy == 0) {
#pragma unroll
            for (int lh = 0; lh < 4; lh++) {
                float ps0 = 0.f, pd0 = 0.f, ps1 = 0.f, pd1 = 0.f;
#pragma unroll
                for (int j = 0; j < 2; j++) {
                    int ni = 2 * lh + j;
                    int c0 = wcol + 8 * ni + 2 * t;
                    float as0 = att_s[c0], as1 = att_s[c0 + 1];
                    float ad0 = att_d[c0], ad1 = att_d[c0 + 1];
                    ps0 += d[mi][ni][0] * as0 + d[mi][ni][1] * as1;
                    pd0 += d[mi][ni][0] * ad0 + d[mi][ni][1] * ad1;
                    ps1 += d[mi][ni][2] * as0 + d[mi][ni][3] * as1;
                    pd1 += d[mi][ni][2] * ad0 + d[mi][ni][3] * ad1;
                }
                ps0 += __shfl_xor_sync(FULL, ps0, 1); ps0 += __shfl_xor_sync(FULL, ps0, 2);
                pd0 += __shfl_xor_sync(FULL, pd0, 1); pd0 += __shfl_xor_sync(FULL, pd0, 2);
                ps1 += __shfl_xor_sync(FULL, ps1, 1); ps1 += __shfl_xor_sync(FULL, ps1, 2);
                pd1 += __shfl_xor_sync(FULL, pd1, 1); pd1 += __shfl_xor_sync(FULL, pd1, 2);
                int head = wcol / 16 + lh;
                if (t == 0) {
                    if (r0 < NN) { g_asrc[r0 * HH + head] = ps0; g_adst[r0 * HH + head] = pd0; }
                    if (r1 < NN) { g_asrc[r1 * HH + head] = ps1; g_adst[r1 * HH + head] = pd1; }
                }
            }
        }
    }
}

// ---------------------------------------------------------------------------
__global__ void k_hist(const int* __restrict__ ei) {
    int e = blockIdx.x * blockDim.x + threadIdx.x;
    if (e < EE) atomicAdd(&g_cnt[ei[EE + e]], 1);
}

__device__ __forceinline__ int block_excl_scan(int v, int* warpsums) {
    int lane = threadIdx.x & 31, wid = threadIdx.x >> 5;
    int x = v;
#pragma unroll
    for (int off = 1; off < 32; off <<= 1) {
        int y = __shfl_up_sync(FULL, x, off);
        if (lane >= off) x += y;
    }
    if (lane == 31) warpsums[wid] = x;
    __syncthreads();
    if (wid == 0) {
        int nw = (blockDim.x + 31) >> 5;
        int s = (lane < nw) ? warpsums[lane] : 0;
#pragma unroll
        for (int off = 1; off < 32; off <<= 1) {
            int y = __shfl_up_sync(FULL, s, off);
            if (lane >= off) s += y;
        }
        warpsums[lane] = s;
    }
    __syncthreads();
    int base = (wid > 0) ? warpsums[wid - 1] : 0;
    return base + x - v;
}

__global__ void k_scan_a() {
    __shared__ int ws[32];
    int i = blockIdx.x * SCAN_T + threadIdx.x;
    int v = (i < NN) ? g_cnt[i] : 0;
    int ex = block_excl_scan(v, ws);
    if (i < NN) g_rowstart[i] = ex;
    if (threadIdx.x == SCAN_T - 1) g_part[blockIdx.x] = ex + v;
}

// scan_c also re-zeroes g_cnt for the next run (deterministic per-run state).
__global__ void k_scan_c() {
    __shared__ int parts[NB];
    if (threadIdx.x < NB) parts[threadIdx.x] = g_part[threadIdx.x];
    __syncthreads();
    int pre = 0;
    for (int j = 0; j < NB; j++)
        if (j < blockIdx.x) pre += parts[j];
    int i = blockIdx.x * SCAN_T + threadIdx.x;
    if (i < NN) {
        int r = g_rowstart[i] + pre;
        g_rowstart[i] = r;
        g_cursor[i] = r;
        g_cnt[i] = 0;
    }
    if (i == 0) g_rowstart[NN] = EE;
}

__global__ void k_fill(const int* __restrict__ ei) {
    int e = blockIdx.x * blockDim.x + threadIdx.x;
    if (e >= EE) return;
    int s = ei[e], d = ei[EE + e];
    int pos = atomicAdd(&g_cursor[d], 1);
    g_csr[pos] = s;
}

// ---------------------------------------------------------------------------
__device__ __forceinline__ void acc_h(int s, int lane, float ex,
                                      float& a0, float& a1, float& a2, float& a3) {
    uint2 u = *(const uint2*)&g_hh[s * 64 + lane * 2];
    float2 f0 = __half22float2(*reinterpret_cast<__half2*>(&u.x));
    float2 f1 = __half22float2(*reinterpret_cast<__half2*>(&u.y));
    a0 += ex * f0.x; a1 += ex * f0.y; a2 += ex * f1.x; a3 += ex * f1.y;
}

__global__ void __launch_bounds__(256)
k_gather(const float* __restrict__ bias,
         const float* __restrict__ gamma,
         const float* __restrict__ beta,
         float* __restrict__ out) {
    int t = blockIdx.x * blockDim.x + threadIdx.x;
    int n = t >> 5, lane = t & 31;
    if (n >= NN) return;
    int head = lane >> 2;

    float adn = g_adst[n * HH + head];
    float a0 = 0.f, a1 = 0.f, a2 = 0.f, a3 = 0.f, den = 0.f;

    {   // self-loop
        float e = g_asrc[n * HH + head] + adn;
        e = e > 0.f ? e : NEG * e;
        float ex = __expf(e);
        acc_h(n, lane, ex, a0, a1, a2, a3);
        den += ex;
    }

    int start = g_rowstart[n], end = g_rowstart[n + 1];
    for (int base = start; base < end; base += 32) {
        int j = base + lane;
        int sj = (j < end) ? g_csr[j] : 0;
        int m = min(32, end - base);
        int k = 0;
        for (; k + 4 <= m; k += 4) {
            int s0 = __shfl_sync(FULL, sj, k);
            int s1 = __shfl_sync(FULL, sj, k + 1);
            int s2 = __shfl_sync(FULL, sj, k + 2);
            int s3 = __shfl_sync(FULL, sj, k + 3);
            float e0 = g_asrc[s0 * HH + head] + adn;
            float e1 = g_asrc[s1 * HH + head] + adn;
            float e2 = g_asrc[s2 * HH + head] + adn;
            float e3 = g_asrc[s3 * HH + head] + adn;
            e0 = e0 > 0.f ? e0 : NEG * e0;
            e1 = e1 > 0.f ? e1 : NEG * e1;
            e2 = e2 > 0.f ? e2 : NEG * e2;
            e3 = e3 > 0.f ? e3 : NEG * e3;
            float x0 = __expf(e0), x1 = __expf(e1);
            float x2 = __expf(e2), x3 = __expf(e3);
            acc_h(s0, lane, x0, a0, a1, a2, a3);
            acc_h(s1, lane, x1, a0, a1, a2, a3);
            acc_h(s2, lane, x2, a0, a1, a2, a3);
            acc_h(s3, lane, x3, a0, a1, a2, a3);
            den += x0 + x1 + x2 + x3;
        }
        for (; k < m; k++) {
            int s = __shfl_sync(FULL, sj, k);
            float e = g_asrc[s * HH + head] + adn;
            e = e > 0.f ? e : NEG * e;
            float ex = __expf(e);
            acc_h(s, lane, ex, a0, a1, a2, a3);
            den += ex;
        }
    }

    float inv = 1.0f / den;
    uint2 us = *(const uint2*)&g_sk[n * 64 + lane * 2];
    float2 s0 = __half22float2(*reinterpret_cast<__half2*>(&us.x));
    float2 s1 = __half22float2(*reinterpret_cast<__half2*>(&us.y));
    float4 b  = *(const float4*)&bias[lane * 4];
    float z0 = a0 * inv + b.x + 0.1f * s0.x;
    float z1 = a1 * inv + b.y + 0.1f * s0.y;
    float z2 = a2 * inv + b.z + 0.1f * s1.x;
    float z3 = a3 * inv + b.w + 0.1f * s1.y;

    float sum = z0 + z1 + z2 + z3;
    float sq  = z0 * z0 + z1 * z1 + z2 * z2 + z3 * z3;
#pragma unroll
    for (int off = 16; off >= 1; off >>= 1) {
        sum += __shfl_xor_sync(FULL, sum, off);
        sq  += __shfl_xor_sync(FULL, sq, off);
    }
    float mu   = sum * (1.0f / 128.0f);
    float var  = sq * (1.0f / 128.0f) - mu * mu;
    float rstd = rsqrtf(var + 1e-5f);
    float4 g  = *(const float4*)&gamma[lane * 4];
    float4 be = *(const float4*)&beta[lane * 4];
    float y0 = (z0 - mu) * rstd * g.x + be.x;
    float y1 = (z1 - mu) * rstd * g.y + be.y;
    float y2 = (z2 - mu) * rstd * g.z + be.z;
    float y3 = (z3 - mu) * rstd * g.w + be.w;
    y0 = y0 > 0.f ? y0 : expm1f(y0);
    y1 = y1 > 0.f ? y1 : expm1f(y1);
    y2 = y2 > 0.f ? y2 : expm1f(y2);
    y3 = y3 > 0.f ? y3 : expm1f(y3);
    *(float4*)&out[n * HC + lane * 4] = make_float4(y0, y1, y2, y3);
}

// ---------------------------------------------------------------------------
extern "C" void kernel_launch(void* const* d_in, const int* in_sizes, int n_in,
                              void* d_out, int out_size) {
    const float* x       = (const float*)d_in[0];
    const int*   ei      = (const int*)d_in[1];
    const float* W_gat   = (const float*)d_in[2];
    const float* att_src = (const float*)d_in[3];
    const float* att_dst = (const float*)d_in[4];
    const float* bias    = (const float*)d_in[5];
    const float* W_skip  = (const float*)d_in[6];
    const float* gamma   = (const float*)d_in[7];
    const float* beta    = (const float*)d_in[8];
    float* out = (float*)d_out;

    // One-time setup (first call is the uncaptured correctness run).
    static cudaStream_t s1 = nullptr;
    static cudaEvent_t evFork = nullptr, evJoin = nullptr;
    if (!s1) {
        cudaStreamCreateWithFlags(&s1, cudaStreamNonBlocking);
        cudaEventCreateWithFlags(&evFork, cudaEventDisableTiming);
        cudaEventCreateWithFlags(&evJoin, cudaEventDisableTiming);
        cudaFuncSetAttribute(k_mm, cudaFuncAttributeMaxDynamicSharedMemorySize, SMEM_MM);
    }

    // Fork: CSR build on s1, prep+GEMM on the captured (legacy) stream.
    cudaEventRecord(evFork, 0);
    cudaStreamWaitEvent(s1, evFork, 0);

    k_hist<<<(EE + 255) / 256, 256, 0, s1>>>(ei);
    k_scan_a<<<NB, SCAN_T, 0, s1>>>();
    k_scan_c<<<NB, SCAN_T, 0, s1>>>();
    k_fill<<<(EE + 255) / 256, 256, 0, s1>>>(ei);
    cudaEventRecord(evJoin, s1);

    k_prep<<<(NN * 32 + 255) / 256, 256>>>(x);
    k_prepw<<<(256 * 96 + 255) / 256, 256>>>(W_gat, W_skip);
    k_mm<<<dim3((NN + 127) / 128, 2), 256, SMEM_MM>>>(att_src, att_dst);

    // Join, then gather.
    cudaStreamWaitEvent(0, evJoin, 0);
    k_gather<<<(NN * 32 + 255) / 256, 256>>>(bias, gamma, beta, out);
}